// round 3
// baseline (speedup 1.0000x reference)
#include <cuda_runtime.h>
#include <math.h>

// Problem constants
#define NN   20000      // nodes
#define EE   160000     // edges (without self loops)
#define ETOT 180000     // edges + self loops
#define BB   128        // graphs
#define NGG  10000

// ------------------------- scratch (device globals) -------------------------
__device__ float g_h   [NN * 128];      // current node features
__device__ float g_xw  [NN * 512];      // h @ W  -> (n, h, o)
__device__ float g_t   [NN * 256];      // h @ attA1
__device__ float g_hn  [NN * 128];      // pre-BN layer output
__device__ float g_es  [NN * 4];
__device__ float g_ed  [NN * 4];
__device__ float g_Wt  [128 * 512];     // W transposed to (f, h*128+o)
__device__ int   g_deg [NN];
__device__ int   g_off [NN + 1];
__device__ int   g_cur [NN];
__device__ int   g_csr [ETOT];
__device__ float g_bnsum[128];
__device__ float g_bnsq [128];
__device__ float g_lmu [128];
__device__ float g_linv[128];
__device__ float g_s   [NN];
__device__ int   g_gstart[BB];
__device__ int   g_gend  [BB];
__device__ float g_comb[BB * 192];
__device__ float g_z1p [BB * 256];
__device__ float g_z1  [BB * 256];
__device__ float g_z2p [BB * 128];
__device__ float g_z2  [BB * 128];
__device__ float g_nodebias[NGG];

// ------------------------------- setup kernels -------------------------------
__global__ void init_kernel() {
    int i = blockIdx.x * blockDim.x + threadIdx.x;
    if (i < NN) g_deg[i] = 0;
    if (i < BB) { g_gstart[i] = NN; g_gend[i] = 0; }
}

__global__ void copy_h_kernel(const float4* __restrict__ x) {
    int i = blockIdx.x * blockDim.x + threadIdx.x;
    if (i < NN * 32) ((float4*)g_h)[i] = x[i];
}

__global__ void nodebias_kernel(const float* __restrict__ Gemb) {
    int gid  = blockIdx.x * blockDim.x + threadIdx.x;
    int w    = gid >> 5;
    int lane = gid & 31;
    if (w >= NGG) return;
    float v = Gemb[w * 64 + lane] + Gemb[w * 64 + 32 + lane];
    #pragma unroll
    for (int o = 16; o; o >>= 1) v += __shfl_xor_sync(0xffffffffu, v, o);
    if (lane == 0) g_nodebias[w] = v * (1.0f / 64.0f);
}

__global__ void hist_kernel(const int* __restrict__ ei) {
    int e = blockIdx.x * blockDim.x + threadIdx.x;
    if (e >= ETOT) return;
    int dst = (e < EE) ? ei[EE + e] : (e - EE);
    atomicAdd(&g_deg[dst], 1);
}

__global__ void scan_kernel() {
    __shared__ int sh[1024];
    int t = threadIdx.x;
    int carry = 0;
    for (int base = 0; base < NN; base += 1024) {
        int v = (base + t < NN) ? g_deg[base + t] : 0;
        sh[t] = v;
        __syncthreads();
        for (int o = 1; o < 1024; o <<= 1) {
            int x = 0;
            if (t >= o) x = sh[t - o];
            __syncthreads();
            sh[t] += x;
            __syncthreads();
        }
        if (base + t < NN) {
            int excl = carry + sh[t] - v;
            g_off[base + t] = excl;
            g_cur[base + t] = excl;
        }
        carry += sh[1023];
        __syncthreads();
    }
    if (t == 0) g_off[NN] = carry;
}

__global__ void scatter_kernel(const int* __restrict__ ei) {
    int e = blockIdx.x * blockDim.x + threadIdx.x;
    if (e >= ETOT) return;
    int src, dst;
    if (e < EE) { src = ei[e]; dst = ei[EE + e]; }
    else        { src = e - EE; dst = e - EE; }
    int pos = atomicAdd(&g_cur[dst], 1);
    g_csr[pos] = src;
}

// --------------------- Tensor-core GEMM (3xTF32, K=128) ----------------------
// C[M x NC] = A[M x 128] * B[128 x NC].  fp32 in/out, 3xTF32 split for accuracy.
// Block 128x128, 8 warps (4M x 2N), warp tile 32x64, K-chunk 16.

#define CVT_TF32(dst, src) asm("cvt.rna.tf32.f32 %0, %1;" : "=r"(dst) : "f"(src))

#define MMA8(cr, a, b)                                                         \
    asm volatile("mma.sync.aligned.m16n8k8.row.col.f32.tf32.tf32.f32 "         \
                 "{%0,%1,%2,%3}, {%4,%5,%6,%7}, {%8,%9}, {%0,%1,%2,%3};"       \
                 : "+f"(cr[0]), "+f"(cr[1]), "+f"(cr[2]), "+f"(cr[3])          \
                 : "r"(a[0]), "r"(a[1]), "r"(a[2]), "r"(a[3]),                 \
                   "r"(b[0]), "r"(b[1]))

template <int NC>
__device__ __forceinline__ void gemm_tc_body(const float* __restrict__ A,
                                             const float* __restrict__ B,
                                             float* __restrict__ C, int M) {
    // A smem: [m][k] stride 20 -> frag-read banks (20*gid + k) % 32 injective
    // B smem: [k][n] stride 136 -> frag-read banks (8*k + gid) % 32 injective
    __shared__ float sAhi[128 * 20];
    __shared__ float sAlo[128 * 20];
    __shared__ float sBhi[16 * 136];
    __shared__ float sBlo[16 * 136];

    int tid  = threadIdx.x;
    int lane = tid & 31;
    int warp = tid >> 5;
    int warpM = warp >> 1;          // 0..3
    int warpN = warp & 1;           // 0..1
    int gid = lane >> 2;            // 0..7
    int tq  = lane & 3;             // 0..3
    int row0 = blockIdx.y * 128;
    int col0 = blockIdx.x * 128;

    float c[2][8][4];
    #pragma unroll
    for (int mt = 0; mt < 2; mt++)
        #pragma unroll
        for (int nt = 0; nt < 8; nt++)
            #pragma unroll
            for (int i = 0; i < 4; i++) c[mt][nt][i] = 0.0f;

    int lm  = tid >> 2;             // 0..63  (A loader row)
    int lk4 = (tid & 3) * 4;        // 0,4,8,12
    int bn4 = (tid & 31) * 4;       // B loader col
    int bk  = tid >> 5;             // 0..7   (B loader row)

    for (int k0 = 0; k0 < 128; k0 += 16) {
        // ---- load + split A tile (128 x 16) ----
        #pragma unroll
        for (int hh = 0; hh < 2; hh++) {
            int m = lm + hh * 64;
            float4 v = make_float4(0.f, 0.f, 0.f, 0.f);
            if (row0 + m < M) v = *(const float4*)&A[(row0 + m) * 128 + k0 + lk4];
            float vv[4] = {v.x, v.y, v.z, v.w};
            #pragma unroll
            for (int i = 0; i < 4; i++) {
                unsigned hb; CVT_TF32(hb, vv[i]);
                float hf = __uint_as_float(hb);
                float lo = vv[i] - hf;
                unsigned lb; CVT_TF32(lb, lo);
                sAhi[m * 20 + lk4 + i] = hf;
                sAlo[m * 20 + lk4 + i] = __uint_as_float(lb);
            }
        }
        // ---- load + split B tile (16 x 128) ----
        #pragma unroll
        for (int hh = 0; hh < 2; hh++) {
            int k = bk + hh * 8;
            float4 v = *(const float4*)&B[(k0 + k) * NC + col0 + bn4];
            float vv[4] = {v.x, v.y, v.z, v.w};
            #pragma unroll
            for (int i = 0; i < 4; i++) {
                unsigned hb; CVT_TF32(hb, vv[i]);
                float hf = __uint_as_float(hb);
                float lo = vv[i] - hf;
                unsigned lb; CVT_TF32(lb, lo);
                sBhi[k * 136 + bn4 + i] = hf;
                sBlo[k * 136 + bn4 + i] = __uint_as_float(lb);
            }
        }
        __syncthreads();

        #pragma unroll
        for (int k8 = 0; k8 < 2; k8++) {
            int kb = k8 * 8;
            unsigned ah[2][4], al[2][4];
            #pragma unroll
            for (int mt = 0; mt < 2; mt++) {
                int r = warpM * 32 + mt * 16 + gid;
                ah[mt][0] = __float_as_uint(sAhi[r * 20 + kb + tq]);
                ah[mt][1] = __float_as_uint(sAhi[(r + 8) * 20 + kb + tq]);
                ah[mt][2] = __float_as_uint(sAhi[r * 20 + kb + tq + 4]);
                ah[mt][3] = __float_as_uint(sAhi[(r + 8) * 20 + kb + tq + 4]);
                al[mt][0] = __float_as_uint(sAlo[r * 20 + kb + tq]);
                al[mt][1] = __float_as_uint(sAlo[(r + 8) * 20 + kb + tq]);
                al[mt][2] = __float_as_uint(sAlo[r * 20 + kb + tq + 4]);
                al[mt][3] = __float_as_uint(sAlo[(r + 8) * 20 + kb + tq + 4]);
            }
            unsigned bh[8][2], bl[8][2];
            #pragma unroll
            for (int nt = 0; nt < 8; nt++) {
                int nb = warpN * 64 + nt * 8 + gid;
                bh[nt][0] = __float_as_uint(sBhi[(kb + tq) * 136 + nb]);
                bh[nt][1] = __float_as_uint(sBhi[(kb + tq + 4) * 136 + nb]);
                bl[nt][0] = __float_as_uint(sBlo[(kb + tq) * 136 + nb]);
                bl[nt][1] = __float_as_uint(sBlo[(kb + tq + 4) * 136 + nb]);
            }
            #pragma unroll
            for (int mt = 0; mt < 2; mt++)
                #pragma unroll
                for (int nt = 0; nt < 8; nt++) {
                    MMA8(c[mt][nt], ah[mt], bh[nt]);
                    MMA8(c[mt][nt], ah[mt], bl[nt]);
                    MMA8(c[mt][nt], al[mt], bh[nt]);
                }
        }
        __syncthreads();
    }

    // ---- writeback ----
    #pragma unroll
    for (int mt = 0; mt < 2; mt++) {
        int r = row0 + warpM * 32 + mt * 16 + gid;
        #pragma unroll
        for (int nt = 0; nt < 8; nt++) {
            int cc = col0 + warpN * 64 + nt * 8 + tq * 2;
            if (r < M)
                *(float2*)&C[r * NC + cc] = make_float2(c[mt][nt][0], c[mt][nt][1]);
            if (r + 8 < M)
                *(float2*)&C[(r + 8) * NC + cc] = make_float2(c[mt][nt][2], c[mt][nt][3]);
        }
    }
}

__global__ __launch_bounds__(256, 1) void gemm_xw_kernel() {
    gemm_tc_body<512>(g_h, g_Wt, g_xw, NN);
}
__global__ __launch_bounds__(256, 1) void gemm_att_kernel(const float* __restrict__ attA1) {
    gemm_tc_body<256>(g_h, attA1, g_t, NN);
}

// ------------------------------- GAT per-layer -------------------------------
__global__ void transpose_w_kernel(const float* __restrict__ Wg, int l) {
    int idx = blockIdx.x * blockDim.x + threadIdx.x;
    if (idx >= 128 * 512) return;
    int f = idx >> 9;
    int r = idx & 511;
    int h = r >> 7;
    int o = r & 127;
    g_Wt[idx] = Wg[(((l * 4 + h) * 128) + f) * 128 + o];
}

__global__ void att_coef_kernel(const float* __restrict__ asrc,
                                const float* __restrict__ adst) {
    int gt = blockIdx.x * blockDim.x + threadIdx.x;
    if (gt < 128) { g_bnsum[gt] = 0.f; g_bnsq[gt] = 0.f; }
    int warpId = gt >> 5;
    int lane   = gt & 31;
    int nw = (gridDim.x * blockDim.x) >> 5;
    for (int t = warpId; t < NN * 4; t += nw) {
        int n = t >> 2, h = t & 3;
        const float* xp = &g_xw[n * 512 + h * 128];
        float s1 = 0.f, s2 = 0.f;
        #pragma unroll
        for (int j = 0; j < 4; j++) {
            float xv = xp[lane + 32 * j];
            s1 += xv * asrc[h * 128 + lane + 32 * j];
            s2 += xv * adst[h * 128 + lane + 32 * j];
        }
        #pragma unroll
        for (int o = 16; o; o >>= 1) {
            s1 += __shfl_xor_sync(0xffffffffu, s1, o);
            s2 += __shfl_xor_sync(0xffffffffu, s2, o);
        }
        if (lane == 0) { g_es[t] = s1; g_ed[t] = s2; }
    }
}

__device__ __forceinline__ float lrelu(float v) {
    return v > 0.f ? v : 0.2f * v;
}

__global__ void aggregate_kernel(const float* __restrict__ gbias) {
    int gt   = blockIdx.x * blockDim.x + threadIdx.x;
    int warp = gt >> 5;
    int lane = gt & 31;
    int nw = (gridDim.x * blockDim.x) >> 5;
    // lane owns channels lane*4 .. lane*4+3
    float4 csum = make_float4(0.f, 0.f, 0.f, 0.f);
    float4 csq  = make_float4(0.f, 0.f, 0.f, 0.f);
    float4 gb = ((const float4*)gbias)[lane];
    for (int n = warp; n < NN; n += nw) {
        int o0 = g_off[n], o1 = g_off[n + 1];
        float4 edn = *(const float4*)&g_ed[n * 4];

        // ---- pass 1: per-head max over edges ----
        float m0 = -1e30f, m1 = -1e30f, m2 = -1e30f, m3 = -1e30f;
        for (int e = o0 + lane; e < o1; e += 32) {
            int s = g_csr[e];
            float4 es = *(const float4*)&g_es[s * 4];
            m0 = fmaxf(m0, lrelu(es.x + edn.x));
            m1 = fmaxf(m1, lrelu(es.y + edn.y));
            m2 = fmaxf(m2, lrelu(es.z + edn.z));
            m3 = fmaxf(m3, lrelu(es.w + edn.w));
        }
        #pragma unroll
        for (int o = 16; o; o >>= 1) {
            m0 = fmaxf(m0, __shfl_xor_sync(0xffffffffu, m0, o));
            m1 = fmaxf(m1, __shfl_xor_sync(0xffffffffu, m1, o));
            m2 = fmaxf(m2, __shfl_xor_sync(0xffffffffu, m2, o));
            m3 = fmaxf(m3, __shfl_xor_sync(0xffffffffu, m3, o));
        }

        // ---- pass 2: single edge sweep, float4 gathers ----
        float den[4] = {0.f, 0.f, 0.f, 0.f};
        float4 acc[4];
        #pragma unroll
        for (int h = 0; h < 4; h++) acc[h] = make_float4(0.f, 0.f, 0.f, 0.f);

        for (int e = o0; e < o1; e++) {
            int s = g_csr[e];                       // broadcast load
            float4 es = *(const float4*)&g_es[s * 4];
            float w0 = __expf(lrelu(es.x + edn.x) - m0);
            float w1 = __expf(lrelu(es.y + edn.y) - m1);
            float w2 = __expf(lrelu(es.z + edn.z) - m2);
            float w3 = __expf(lrelu(es.w + edn.w) - m3);
            den[0] += w0; den[1] += w1; den[2] += w2; den[3] += w3;
            const float4* xp = (const float4*)&g_xw[s * 512];
            float wv[4] = {w0, w1, w2, w3};
            #pragma unroll
            for (int h = 0; h < 4; h++) {
                float4 xv = xp[h * 32 + lane];
                acc[h].x += wv[h] * xv.x;
                acc[h].y += wv[h] * xv.y;
                acc[h].z += wv[h] * xv.z;
                acc[h].w += wv[h] * xv.w;
            }
        }

        float i0 = 1.f / den[0], i1 = 1.f / den[1], i2 = 1.f / den[2], i3 = 1.f / den[3];
        float4 v;
        v.x = (acc[0].x * i0 + acc[1].x * i1 + acc[2].x * i2 + acc[3].x * i3) * 0.25f + gb.x;
        v.y = (acc[0].y * i0 + acc[1].y * i1 + acc[2].y * i2 + acc[3].y * i3) * 0.25f + gb.y;
        v.z = (acc[0].z * i0 + acc[1].z * i1 + acc[2].z * i2 + acc[3].z * i3) * 0.25f + gb.z;
        v.w = (acc[0].w * i0 + acc[1].w * i1 + acc[2].w * i2 + acc[3].w * i3) * 0.25f + gb.w;
        *(float4*)&g_hn[n * 128 + lane * 4] = v;
        csum.x += v.x; csum.y += v.y; csum.z += v.z; csum.w += v.w;
        csq.x += v.x * v.x; csq.y += v.y * v.y; csq.z += v.z * v.z; csq.w += v.w * v.w;
    }
    atomicAdd(&g_bnsum[lane * 4 + 0], csum.x);
    atomicAdd(&g_bnsum[lane * 4 + 1], csum.y);
    atomicAdd(&g_bnsum[lane * 4 + 2], csum.z);
    atomicAdd(&g_bnsum[lane * 4 + 3], csum.w);
    atomicAdd(&g_bnsq[lane * 4 + 0], csq.x);
    atomicAdd(&g_bnsq[lane * 4 + 1], csq.y);
    atomicAdd(&g_bnsq[lane * 4 + 2], csq.z);
    atomicAdd(&g_bnsq[lane * 4 + 3], csq.w);
}

__global__ void bn_finalize_kernel() {
    int c = threadIdx.x;  // 128 threads
    float mu  = g_bnsum[c] * (1.0f / NN);
    float var = g_bnsq[c] * (1.0f / NN) - mu * mu;
    g_lmu[c]  = mu;
    g_linv[c] = rsqrtf(var + 1e-5f);
}

__global__ void bn_apply_kernel(const float* __restrict__ scale,
                                const float* __restrict__ bias, int addRes) {
    int idx = blockIdx.x * blockDim.x + threadIdx.x;   // NN*32 float4s
    if (idx >= NN * 32) return;
    int c4 = (idx & 31) * 4;
    float4 v = ((const float4*)g_hn)[idx];
    float4 r;
    r.x = fmaxf((v.x - g_lmu[c4+0]) * g_linv[c4+0] * scale[c4+0] + bias[c4+0], 0.f);
    r.y = fmaxf((v.y - g_lmu[c4+1]) * g_linv[c4+1] * scale[c4+1] + bias[c4+1], 0.f);
    r.z = fmaxf((v.z - g_lmu[c4+2]) * g_linv[c4+2] * scale[c4+2] + bias[c4+2], 0.f);
    r.w = fmaxf((v.w - g_lmu[c4+3]) * g_linv[c4+3] * scale[c4+3] + bias[c4+3], 0.f);
    if (addRes) {
        float4 h = ((const float4*)g_h)[idx];
        r.x += h.x; r.y += h.y; r.z += h.z; r.w += h.w;
    }
    ((float4*)g_h)[idx] = r;
}

// ------------------------------- pooling head -------------------------------
__global__ void score_kernel(const float* __restrict__ ab1,
                             const float* __restrict__ aA2,
                             const float* __restrict__ ab2) {
    int gt   = blockIdx.x * blockDim.x + threadIdx.x;
    int w    = gt >> 5;
    int lane = gt & 31;
    if (w >= NN) return;
    float acc = 0.f;
    #pragma unroll
    for (int j = lane; j < 256; j += 32)
        acc += tanhf(g_t[w * 256 + j] + ab1[j]) * aA2[j];
    #pragma unroll
    for (int o = 16; o; o >>= 1) acc += __shfl_xor_sync(0xffffffffu, acc, o);
    if (lane == 0) g_s[w] = acc + ab2[0];
}

__global__ void bounds_kernel(const int* __restrict__ batch) {
    int n = blockIdx.x * blockDim.x + threadIdx.x;
    if (n >= NN) return;
    int g = batch[n];
    atomicMin(&g_gstart[g], n);
    atomicMax(&g_gend[g], n + 1);
}

__global__ void pool_kernel(const int* __restrict__ brand0,
                            const int* __restrict__ brand1,
                            const float* __restrict__ Eb0,
                            const float* __restrict__ Eb1) {
    int g = blockIdx.x;     // BB blocks
    int t = threadIdx.x;    // 128 threads
    __shared__ float red[128];
    int st = g_gstart[g], en = g_gend[g];

    float m = -1e30f;
    for (int n = st + t; n < en; n += 128) m = fmaxf(m, g_s[n]);
    red[t] = m; __syncthreads();
    for (int o = 64; o; o >>= 1) { if (t < o) red[t] = fmaxf(red[t], red[t + o]); __syncthreads(); }
    m = red[0]; __syncthreads();

    float d = 0.f;
    for (int n = st + t; n < en; n += 128) d += __expf(g_s[n] - m);
    red[t] = d; __syncthreads();
    for (int o = 64; o; o >>= 1) { if (t < o) red[t] += red[t + o]; __syncthreads(); }
    d = red[0]; __syncthreads();

    float inv = (en > st) ? 1.0f / d : 0.0f;
    float acc = 0.f;
    for (int n = st; n < en; n++) {
        float w = __expf(g_s[n] - m) * inv;
        acc += w * g_h[n * 128 + t];
    }
    g_comb[g * 192 + t] = acc;
    if (t < 32)       g_comb[g * 192 + 128 + t]        = Eb0[brand0[g] * 32 + t];
    else if (t < 64)  g_comb[g * 192 + 160 + (t - 32)] = Eb1[brand1[g] * 32 + (t - 32)];
}

// --------------------------------- MLP head ---------------------------------
__global__ void mlp1_kernel(const float* __restrict__ P1w, const float* __restrict__ P1b) {
    int g = blockIdx.x;     // BB blocks
    int j = threadIdx.x;    // 256 threads
    __shared__ float cs[192];
    if (j < 192) cs[j] = g_comb[g * 192 + j];
    __syncthreads();
    float a = P1b[j];
    #pragma unroll 8
    for (int k = 0; k < 192; k++) a += cs[k] * P1w[k * 256 + j];
    g_z1p[g * 256 + j] = a;
}

__global__ void bnrelu1_kernel(const float* __restrict__ sc, const float* __restrict__ bi) {
    int j = blockIdx.x;     // 256 blocks (features)
    int t = threadIdx.x;    // 128 threads (rows)
    __shared__ float red[128];
    float x = g_z1p[t * 256 + j];
    red[t] = x; __syncthreads();
    for (int o = 64; o; o >>= 1) { if (t < o) red[t] += red[t + o]; __syncthreads(); }
    float mu = red[0] * (1.0f / 128.0f); __syncthreads();
    red[t] = x * x; __syncthreads();
    for (int o = 64; o; o >>= 1) { if (t < o) red[t] += red[t + o]; __syncthreads(); }
    float var = red[0] * (1.0f / 128.0f) - mu * mu;
    float v = (x - mu) * rsqrtf(var + 1e-5f) * sc[j] + bi[j];
    g_z1[t * 256 + j] = fmaxf(v, 0.0f);
}

__global__ void mlp2_kernel(const float* __restrict__ P2w, const float* __restrict__ P2b) {
    int g = blockIdx.x;     // BB blocks
    int j = threadIdx.x;    // 128 threads
    __shared__ float zs[256];
    zs[j]       = g_z1[g * 256 + j];
    zs[j + 128] = g_z1[g * 256 + j + 128];
    __syncthreads();
    float a = P2b[j];
    #pragma unroll 8
    for (int k = 0; k < 256; k++) a += zs[k] * P2w[k * 128 + j];
    g_z2p[g * 128 + j] = a;
}

__global__ void bnrelu2_kernel(const float* __restrict__ sc, const float* __restrict__ bi) {
    int j = blockIdx.x;     // 128 blocks
    int t = threadIdx.x;    // 128 threads
    __shared__ float red[128];
    float x = g_z2p[t * 128 + j];
    red[t] = x; __syncthreads();
    for (int o = 64; o; o >>= 1) { if (t < o) red[t] += red[t + o]; __syncthreads(); }
    float mu = red[0] * (1.0f / 128.0f); __syncthreads();
    red[t] = x * x; __syncthreads();
    for (int o = 64; o; o >>= 1) { if (t < o) red[t] += red[t + o]; __syncthreads(); }
    float var = red[0] * (1.0f / 128.0f) - mu * mu;
    float v = (x - mu) * rsqrtf(var + 1e-5f) * sc[j] + bi[j];
    g_z2[t * 128 + j] = fmaxf(v, 0.0f);
}

__global__ void final_kernel(const float* __restrict__ P3w,
                             const float* __restrict__ P3b,
                             float* __restrict__ out) {
    __shared__ float zs[16][128];
    int col = blockIdx.x * 256 + threadIdx.x;
    int r0  = blockIdx.y * 16;
    for (int i = threadIdx.x; i < 16 * 128; i += 256) {
        int r = i >> 7, k = i & 127;
        zs[r][k] = g_z2[(r0 + r) * 128 + k];
    }
    __syncthreads();
    if (col >= NGG) return;
    float acc[16];
    #pragma unroll
    for (int r = 0; r < 16; r++) acc[r] = 0.f;
    for (int k = 0; k < 128; k++) {
        float b = P3w[k * NGG + col];
        #pragma unroll
        for (int r = 0; r < 16; r++) acc[r] += zs[r][k] * b;
    }
    float add = P3b[col] + 0.1f * g_nodebias[col];
    #pragma unroll
    for (int r = 0; r < 16; r++) out[(r0 + r) * NGG + col] = acc[r] + add;
}

// ------------------------------- kernel_launch -------------------------------
extern "C" void kernel_launch(void* const* d_in, const int* in_sizes, int n_in,
                              void* d_out, int out_size) {
    const float* x        = (const float*)d_in[0];
    const int*   ei       = (const int*)  d_in[1];
    const int*   batch    = (const int*)  d_in[2];
    const int*   brand0   = (const int*)  d_in[3];
    const int*   brand1   = (const int*)  d_in[4];
    const float* Wg       = (const float*)d_in[5];
    const float* att_src  = (const float*)d_in[6];
    const float* att_dst  = (const float*)d_in[7];
    const float* gat_bias = (const float*)d_in[8];
    const float* bn_scale = (const float*)d_in[9];
    const float* bn_bias  = (const float*)d_in[10];
    const float* attA1    = (const float*)d_in[11];
    const float* attb1    = (const float*)d_in[12];
    const float* attA2    = (const float*)d_in[13];
    const float* attb2    = (const float*)d_in[14];
    const float* Eb0      = (const float*)d_in[15];
    const float* Eb1      = (const float*)d_in[16];
    const float* P1w      = (const float*)d_in[17];
    const float* P1b      = (const float*)d_in[18];
    const float* pbn1_s   = (const float*)d_in[19];
    const float* pbn1_b   = (const float*)d_in[20];
    const float* P2w      = (const float*)d_in[21];
    const float* P2b      = (const float*)d_in[22];
    const float* pbn2_s   = (const float*)d_in[23];
    const float* pbn2_b   = (const float*)d_in[24];
    const float* P3w      = (const float*)d_in[25];
    const float* P3b      = (const float*)d_in[26];
    const float* Gemb     = (const float*)d_in[27];
    float* out = (float*)d_out;

    // setup
    init_kernel<<<(NN + 255) / 256, 256>>>();
    copy_h_kernel<<<(NN * 32 + 255) / 256, 256>>>((const float4*)x);
    nodebias_kernel<<<(NGG * 32 + 255) / 256, 256>>>(Gemb);
    hist_kernel<<<(ETOT + 255) / 256, 256>>>(ei);
    scan_kernel<<<1, 1024>>>();
    scatter_kernel<<<(ETOT + 255) / 256, 256>>>(ei);

    // GAT layers
    for (int l = 0; l < 3; l++) {
        transpose_w_kernel<<<(128 * 512 + 255) / 256, 256>>>(Wg, l);
        gemm_xw_kernel<<<dim3(4, (NN + 127) / 128), 256>>>();
        att_coef_kernel<<<256, 256>>>(att_src + l * 512, att_dst + l * 512);
        aggregate_kernel<<<256, 256>>>(gat_bias + l * 128);
        bn_finalize_kernel<<<1, 128>>>();
        bn_apply_kernel<<<(NN * 32 + 255) / 256, 256>>>(bn_scale + l * 128,
                                                        bn_bias + l * 128,
                                                        l > 0 ? 1 : 0);
    }

    // attention pooling
    gemm_att_kernel<<<dim3(2, (NN + 127) / 128), 256>>>(attA1);
    score_kernel<<<(NN * 32 + 255) / 256, 256>>>(attb1, attA2, attb2);
    bounds_kernel<<<(NN + 255) / 256, 256>>>(batch);
    pool_kernel<<<BB, 128>>>(brand0, brand1, Eb0, Eb1);

    // MLP head
    mlp1_kernel<<<BB, 256>>>(P1w, P1b);
    bnrelu1_kernel<<<256, 128>>>(pbn1_s, pbn1_b);
    mlp2_kernel<<<BB, 128>>>(P2w, P2b);
    bnrelu2_kernel<<<128, 128>>>(pbn2_s, pbn2_b);
    final_kernel<<<dim3((NGG + 255) / 256, 8), 256>>>(P3w, P3b, out);
}

// round 4
// speedup vs baseline: 1.2361x; 1.2361x over previous
#include <cuda_runtime.h>
#include <cuda_bf16.h>
#include <math.h>

// Problem constants
#define NN   20000      // nodes
#define EE   160000     // edges (without self loops)
#define ETOT 180000     // edges + self loops
#define BB   128        // graphs
#define NGG  10000

// ------------------------- scratch (device globals) -------------------------
__device__ float    g_h   [NN * 128];   // current node features
__device__ unsigned g_hhi [NN * 64];    // h split hi (2 bf16 per uint)
__device__ unsigned g_hlo [NN * 64];    // h split lo
__device__ float    g_xw  [NN * 512];   // h @ W  -> (n, h, o)
__device__ float    g_t   [NN * 256];   // h @ attA1
__device__ float    g_hn  [NN * 128];   // pre-BN layer output
__device__ float    g_es  [NN * 4];
__device__ float    g_ed  [NN * 4];
__device__ unsigned g_Wnhi[512 * 64];   // W as [h*128+o][f], bf16 hi packed
__device__ unsigned g_Wnlo[512 * 64];
__device__ unsigned g_A1hi[256 * 64];   // attA1 as [n][k], bf16 hi packed
__device__ unsigned g_A1lo[256 * 64];
__device__ int   g_deg [NN];
__device__ int   g_off [NN + 1];
__device__ int   g_cur [NN];
__device__ int   g_csr [ETOT];
__device__ int   g_bsum[20];
__device__ int   g_bpre[20];
__device__ float g_bnsum[128];
__device__ float g_bnsq [128];
__device__ float g_lmu [128];
__device__ float g_linv[128];
__device__ float g_s   [NN];
__device__ int   g_gstart[BB];
__device__ int   g_gend  [BB];
__device__ float g_comb[BB * 192];
__device__ float g_z1p [BB * 256];
__device__ float g_z1  [BB * 256];
__device__ float g_z2p [BB * 128];
__device__ float g_z2  [BB * 128];
__device__ float g_nodebias[NGG];

// --------------------------- bf16 split helper -------------------------------
__device__ __forceinline__ void split2(float x, float y, unsigned& hi, unsigned& lo) {
    __nv_bfloat16 hx = __float2bfloat16_rn(x);
    __nv_bfloat16 hy = __float2bfloat16_rn(y);
    float rx = x - __bfloat162float(hx);
    float ry = y - __bfloat162float(hy);
    __nv_bfloat16 lx = __float2bfloat16_rn(rx);
    __nv_bfloat16 ly = __float2bfloat16_rn(ry);
    hi = (unsigned)__bfloat16_as_ushort(hx) | ((unsigned)__bfloat16_as_ushort(hy) << 16);
    lo = (unsigned)__bfloat16_as_ushort(lx) | ((unsigned)__bfloat16_as_ushort(ly) << 16);
}

// ------------------------------- setup kernels -------------------------------
__global__ void init_kernel() {
    int i = blockIdx.x * blockDim.x + threadIdx.x;
    if (i < NN) g_deg[i] = 0;
    if (i < BB) { g_gstart[i] = NN; g_gend[i] = 0; }
}

__global__ void copy_h_kernel(const float4* __restrict__ x) {
    int i = blockIdx.x * blockDim.x + threadIdx.x;
    if (i >= NN * 32) return;
    float4 v = x[i];
    ((float4*)g_h)[i] = v;
    uint2 hi, lo;
    split2(v.x, v.y, hi.x, lo.x);
    split2(v.z, v.w, hi.y, lo.y);
    ((uint2*)g_hhi)[i] = hi;
    ((uint2*)g_hlo)[i] = lo;
}

__global__ void nodebias_kernel(const float* __restrict__ Gemb) {
    int gid  = blockIdx.x * blockDim.x + threadIdx.x;
    int w    = gid >> 5;
    int lane = gid & 31;
    if (w >= NGG) return;
    float v = Gemb[w * 64 + lane] + Gemb[w * 64 + 32 + lane];
    #pragma unroll
    for (int o = 16; o; o >>= 1) v += __shfl_xor_sync(0xffffffffu, v, o);
    if (lane == 0) g_nodebias[w] = v * (1.0f / 64.0f);
}

__global__ void hist_kernel(const int* __restrict__ ei) {
    int e = blockIdx.x * blockDim.x + threadIdx.x;
    if (e >= ETOT) return;
    int dst = (e < EE) ? ei[EE + e] : (e - EE);
    atomicAdd(&g_deg[dst], 1);
}

__global__ void scan1_kernel() {   // 20 blocks x 1024
    __shared__ int sh[1024];
    int b = blockIdx.x, t = threadIdx.x;
    int i = b * 1024 + t;
    int v = (i < NN) ? g_deg[i] : 0;
    sh[t] = v;
    __syncthreads();
    for (int o = 1; o < 1024; o <<= 1) {
        int xv = (t >= o) ? sh[t - o] : 0;
        __syncthreads();
        sh[t] += xv;
        __syncthreads();
    }
    if (i < NN) g_off[i] = sh[t] - v;      // exclusive within chunk
    if (t == 1023) g_bsum[b] = sh[1023];
}

__global__ void scan2_kernel() {   // 1 block, 32 threads
    int t = threadIdx.x;
    int v = (t < 20) ? g_bsum[t] : 0;
    #pragma unroll
    for (int o = 1; o < 32; o <<= 1) {
        int xv = __shfl_up_sync(0xffffffffu, v, o);
        if (t >= o) v += xv;
    }
    if (t < 20) g_bpre[t] = v - g_bsum[t];
    if (t == 19) g_off[NN] = v;
}

__global__ void scan3_kernel() {   // NN threads
    int i = blockIdx.x * blockDim.x + threadIdx.x;
    if (i >= NN) return;
    int val = g_off[i] + g_bpre[i >> 10];
    g_off[i] = val;
    g_cur[i] = val;
}

__global__ void scatter_kernel(const int* __restrict__ ei) {
    int e = blockIdx.x * blockDim.x + threadIdx.x;
    if (e >= ETOT) return;
    int src, dst;
    if (e < EE) { src = ei[e]; dst = ei[EE + e]; }
    else        { src = e - EE; dst = e - EE; }
    int pos = atomicAdd(&g_cur[dst], 1);
    g_csr[pos] = src;
}

// -------------------- BF16 tensor-core GEMM (3x split, K=128) ----------------
// C[M x NC] = A[M x 128] * B[128 x NC].  A = g_hhi/g_hlo (packed bf16x2),
// B given as [n][k] packed bf16x2 (64 uints per row).
// Block: 128 rows x 64 cols, 8 warps (one 16-row band each), K staged fully.

#define MMA_BF16(c, a0, a1, a2, a3, b0, b1)                                    \
    asm volatile("mma.sync.aligned.m16n8k16.row.col.f32.bf16.bf16.f32 "        \
                 "{%0,%1,%2,%3}, {%4,%5,%6,%7}, {%8,%9}, {%0,%1,%2,%3};"       \
                 : "+f"(c[0]), "+f"(c[1]), "+f"(c[2]), "+f"(c[3])              \
                 : "r"(a0), "r"(a1), "r"(a2), "r"(a3), "r"(b0), "r"(b1))

template <int NC>
__global__ __launch_bounds__(256) void gemm_bf16_kernel(
        const unsigned* __restrict__ Bhi, const unsigned* __restrict__ Blo,
        float* __restrict__ C) {
    __shared__ unsigned sBhi[64][68];   // [n][k-word], pad 4 -> conflict-free
    __shared__ unsigned sBlo[64][68];
    int tid  = threadIdx.x;
    int col0 = blockIdx.x * 64;

    for (int i = tid; i < 1024; i += 256) {
        int n = i >> 4, q = (i & 15) * 4;
        *(uint4*)&sBhi[n][q] = *(const uint4*)&Bhi[(col0 + n) * 64 + q];
        *(uint4*)&sBlo[n][q] = *(const uint4*)&Blo[(col0 + n) * 64 + q];
    }
    __syncthreads();

    int lane = tid & 31, warp = tid >> 5;
    int gid = lane >> 2, tq = lane & 3;
    int ra = blockIdx.y * 128 + warp * 16 + gid;
    int rb = ra + 8;
    bool va = ra < NN, vb = rb < NN;

    float acc[8][4];
    #pragma unroll
    for (int nt = 0; nt < 8; nt++)
        #pragma unroll
        for (int i = 0; i < 4; i++) acc[nt][i] = 0.0f;

    #pragma unroll
    for (int kc = 0; kc < 8; kc++) {
        int base = kc * 8 + tq;
        unsigned ah0 = 0, ah1 = 0, ah2 = 0, ah3 = 0;
        unsigned al0 = 0, al1 = 0, al2 = 0, al3 = 0;
        if (va) {
            ah0 = g_hhi[ra * 64 + base];     ah2 = g_hhi[ra * 64 + base + 4];
            al0 = g_hlo[ra * 64 + base];     al2 = g_hlo[ra * 64 + base + 4];
        }
        if (vb) {
            ah1 = g_hhi[rb * 64 + base];     ah3 = g_hhi[rb * 64 + base + 4];
            al1 = g_hlo[rb * 64 + base];     al3 = g_hlo[rb * 64 + base + 4];
        }
        #pragma unroll
        for (int nt = 0; nt < 8; nt++) {
            int n = nt * 8 + gid;
            unsigned bh0 = sBhi[n][kc * 8 + tq];
            unsigned bh1 = sBhi[n][kc * 8 + 4 + tq];
            unsigned bl0 = sBlo[n][kc * 8 + tq];
            unsigned bl1 = sBlo[n][kc * 8 + 4 + tq];
            MMA_BF16(acc[nt], ah0, ah1, ah2, ah3, bh0, bh1);
            MMA_BF16(acc[nt], ah0, ah1, ah2, ah3, bl0, bl1);
            MMA_BF16(acc[nt], al0, al1, al2, al3, bh0, bh1);
        }
    }

    #pragma unroll
    for (int nt = 0; nt < 8; nt++) {
        int cc = col0 + nt * 8 + tq * 2;
        if (va) *(float2*)&C[ra * NC + cc] = make_float2(acc[nt][0], acc[nt][1]);
        if (vb) *(float2*)&C[rb * NC + cc] = make_float2(acc[nt][2], acc[nt][3]);
    }
}

// ------------------------------- GAT per-layer -------------------------------
// W -> [h*128+o][f] bf16 hi/lo, packed 2 f per uint
__global__ void transpose_w_kernel(const float* __restrict__ Wg, int l) {
    int idx = blockIdx.x * blockDim.x + threadIdx.x;   // 512*64
    if (idx >= 512 * 64) return;
    int hn = idx >> 6;          // h*128 + o
    int f  = (idx & 63) * 2;
    int h = hn >> 7, o = hn & 127;
    const float* base = Wg + ((l * 4 + h) * 128) * 128 + o;
    float v0 = base[f * 128];
    float v1 = base[(f + 1) * 128];
    unsigned hi, lo;
    split2(v0, v1, hi, lo);
    g_Wnhi[idx] = hi;
    g_Wnlo[idx] = lo;
}

// attA1 (128 x 256) -> [n][k] bf16 hi/lo
__global__ void a1prep_kernel(const float* __restrict__ attA1) {
    int idx = blockIdx.x * blockDim.x + threadIdx.x;   // 256*64
    if (idx >= 256 * 64) return;
    int n = idx >> 6;
    int k = (idx & 63) * 2;
    float v0 = attA1[k * 256 + n];
    float v1 = attA1[(k + 1) * 256 + n];
    unsigned hi, lo;
    split2(v0, v1, hi, lo);
    g_A1hi[idx] = hi;
    g_A1lo[idx] = lo;
}

__global__ void att_coef_kernel(const float* __restrict__ asrc,
                                const float* __restrict__ adst) {
    int gt = blockIdx.x * blockDim.x + threadIdx.x;
    if (gt < 128) { g_bnsum[gt] = 0.f; g_bnsq[gt] = 0.f; }
    int warpId = gt >> 5;
    int lane   = gt & 31;
    int nw = (gridDim.x * blockDim.x) >> 5;
    for (int t = warpId; t < NN * 4; t += nw) {
        int n = t >> 2, h = t & 3;
        const float* xp = &g_xw[n * 512 + h * 128];
        float s1 = 0.f, s2 = 0.f;
        #pragma unroll
        for (int j = 0; j < 4; j++) {
            float xv = xp[lane + 32 * j];
            s1 += xv * asrc[h * 128 + lane + 32 * j];
            s2 += xv * adst[h * 128 + lane + 32 * j];
        }
        #pragma unroll
        for (int o = 16; o; o >>= 1) {
            s1 += __shfl_xor_sync(0xffffffffu, s1, o);
            s2 += __shfl_xor_sync(0xffffffffu, s2, o);
        }
        if (lane == 0) { g_es[t] = s1; g_ed[t] = s2; }
    }
}

__device__ __forceinline__ float lrelu(float v) {
    return v > 0.f ? v : 0.2f * v;
}

__global__ void aggregate_kernel(const float* __restrict__ gbias) {
    int gt   = blockIdx.x * blockDim.x + threadIdx.x;
    int warp = gt >> 5;
    int lane = gt & 31;
    int nw = (gridDim.x * blockDim.x) >> 5;
    float4 csum = make_float4(0.f, 0.f, 0.f, 0.f);
    float4 csq  = make_float4(0.f, 0.f, 0.f, 0.f);
    float4 gb = ((const float4*)gbias)[lane];
    for (int n = warp; n < NN; n += nw) {
        int o0 = g_off[n], o1 = g_off[n + 1];
        float4 edn = *(const float4*)&g_ed[n * 4];

        float m0 = -1e30f, m1 = -1e30f, m2 = -1e30f, m3 = -1e30f;
        for (int e = o0 + lane; e < o1; e += 32) {
            int s = g_csr[e];
            float4 es = *(const float4*)&g_es[s * 4];
            m0 = fmaxf(m0, lrelu(es.x + edn.x));
            m1 = fmaxf(m1, lrelu(es.y + edn.y));
            m2 = fmaxf(m2, lrelu(es.z + edn.z));
            m3 = fmaxf(m3, lrelu(es.w + edn.w));
        }
        #pragma unroll
        for (int o = 16; o; o >>= 1) {
            m0 = fmaxf(m0, __shfl_xor_sync(0xffffffffu, m0, o));
            m1 = fmaxf(m1, __shfl_xor_sync(0xffffffffu, m1, o));
            m2 = fmaxf(m2, __shfl_xor_sync(0xffffffffu, m2, o));
            m3 = fmaxf(m3, __shfl_xor_sync(0xffffffffu, m3, o));
        }

        float den[4] = {0.f, 0.f, 0.f, 0.f};
        float4 acc[4];
        #pragma unroll
        for (int h = 0; h < 4; h++) acc[h] = make_float4(0.f, 0.f, 0.f, 0.f);

        for (int e = o0; e < o1; e++) {
            int s = g_csr[e];
            float4 es = *(const float4*)&g_es[s * 4];
            float w0 = __expf(lrelu(es.x + edn.x) - m0);
            float w1 = __expf(lrelu(es.y + edn.y) - m1);
            float w2 = __expf(lrelu(es.z + edn.z) - m2);
            float w3 = __expf(lrelu(es.w + edn.w) - m3);
            den[0] += w0; den[1] += w1; den[2] += w2; den[3] += w3;
            const float4* xp = (const float4*)&g_xw[s * 512];
            float wv[4] = {w0, w1, w2, w3};
            #pragma unroll
            for (int h = 0; h < 4; h++) {
                float4 xv = xp[h * 32 + lane];
                acc[h].x += wv[h] * xv.x;
                acc[h].y += wv[h] * xv.y;
                acc[h].z += wv[h] * xv.z;
                acc[h].w += wv[h] * xv.w;
            }
        }

        float i0 = 1.f / den[0], i1 = 1.f / den[1], i2 = 1.f / den[2], i3 = 1.f / den[3];
        float4 v;
        v.x = (acc[0].x * i0 + acc[1].x * i1 + acc[2].x * i2 + acc[3].x * i3) * 0.25f + gb.x;
        v.y = (acc[0].y * i0 + acc[1].y * i1 + acc[2].y * i2 + acc[3].y * i3) * 0.25f + gb.y;
        v.z = (acc[0].z * i0 + acc[1].z * i1 + acc[2].z * i2 + acc[3].z * i3) * 0.25f + gb.z;
        v.w = (acc[0].w * i0 + acc[1].w * i1 + acc[2].w * i2 + acc[3].w * i3) * 0.25f + gb.w;
        *(float4*)&g_hn[n * 128 + lane * 4] = v;
        csum.x += v.x; csum.y += v.y; csum.z += v.z; csum.w += v.w;
        csq.x += v.x * v.x; csq.y += v.y * v.y; csq.z += v.z * v.z; csq.w += v.w * v.w;
    }
    atomicAdd(&g_bnsum[lane * 4 + 0], csum.x);
    atomicAdd(&g_bnsum[lane * 4 + 1], csum.y);
    atomicAdd(&g_bnsum[lane * 4 + 2], csum.z);
    atomicAdd(&g_bnsum[lane * 4 + 3], csum.w);
    atomicAdd(&g_bnsq[lane * 4 + 0], csq.x);
    atomicAdd(&g_bnsq[lane * 4 + 1], csq.y);
    atomicAdd(&g_bnsq[lane * 4 + 2], csq.z);
    atomicAdd(&g_bnsq[lane * 4 + 3], csq.w);
}

__global__ void bn_finalize_kernel() {
    int c = threadIdx.x;  // 128 threads
    float mu  = g_bnsum[c] * (1.0f / NN);
    float var = g_bnsq[c] * (1.0f / NN) - mu * mu;
    g_lmu[c]  = mu;
    g_linv[c] = rsqrtf(var + 1e-5f);
}

__global__ void bn_apply_kernel(const float* __restrict__ scale,
                                const float* __restrict__ bias, int addRes) {
    int idx = blockIdx.x * blockDim.x + threadIdx.x;   // NN*32 float4s
    if (idx >= NN * 32) return;
    int c4 = (idx & 31) * 4;
    float4 v = ((const float4*)g_hn)[idx];
    float4 r;
    r.x = fmaxf((v.x - g_lmu[c4+0]) * g_linv[c4+0] * scale[c4+0] + bias[c4+0], 0.f);
    r.y = fmaxf((v.y - g_lmu[c4+1]) * g_linv[c4+1] * scale[c4+1] + bias[c4+1], 0.f);
    r.z = fmaxf((v.z - g_lmu[c4+2]) * g_linv[c4+2] * scale[c4+2] + bias[c4+2], 0.f);
    r.w = fmaxf((v.w - g_lmu[c4+3]) * g_linv[c4+3] * scale[c4+3] + bias[c4+3], 0.f);
    if (addRes) {
        float4 h = ((const float4*)g_h)[idx];
        r.x += h.x; r.y += h.y; r.z += h.z; r.w += h.w;
    }
    ((float4*)g_h)[idx] = r;
    uint2 hi, lo;
    split2(r.x, r.y, hi.x, lo.x);
    split2(r.z, r.w, hi.y, lo.y);
    ((uint2*)g_hhi)[idx] = hi;
    ((uint2*)g_hlo)[idx] = lo;
}

// ------------------------------- pooling head -------------------------------
__global__ void score_kernel(const float* __restrict__ ab1,
                             const float* __restrict__ aA2,
                             const float* __restrict__ ab2) {
    int gt   = blockIdx.x * blockDim.x + threadIdx.x;
    int w    = gt >> 5;
    int lane = gt & 31;
    if (w >= NN) return;
    float acc = 0.f;
    #pragma unroll
    for (int j = lane; j < 256; j += 32)
        acc += tanhf(g_t[w * 256 + j] + ab1[j]) * aA2[j];
    #pragma unroll
    for (int o = 16; o; o >>= 1) acc += __shfl_xor_sync(0xffffffffu, acc, o);
    if (lane == 0) g_s[w] = acc + ab2[0];
}

__global__ void bounds_kernel(const int* __restrict__ batch) {
    int n = blockIdx.x * blockDim.x + threadIdx.x;
    if (n >= NN) return;
    int g = batch[n];
    atomicMin(&g_gstart[g], n);
    atomicMax(&g_gend[g], n + 1);
}

__global__ void pool_kernel(const int* __restrict__ brand0,
                            const int* __restrict__ brand1,
                            const float* __restrict__ Eb0,
                            const float* __restrict__ Eb1) {
    int g = blockIdx.x;     // BB blocks
    int t = threadIdx.x;    // 128 threads
    __shared__ float red[128];
    int st = g_gstart[g], en = g_gend[g];

    float m = -1e30f;
    for (int n = st + t; n < en; n += 128) m = fmaxf(m, g_s[n]);
    red[t] = m; __syncthreads();
    for (int o = 64; o; o >>= 1) { if (t < o) red[t] = fmaxf(red[t], red[t + o]); __syncthreads(); }
    m = red[0]; __syncthreads();

    float d = 0.f;
    for (int n = st + t; n < en; n += 128) d += __expf(g_s[n] - m);
    red[t] = d; __syncthreads();
    for (int o = 64; o; o >>= 1) { if (t < o) red[t] += red[t + o]; __syncthreads(); }
    d = red[0]; __syncthreads();

    float inv = (en > st) ? 1.0f / d : 0.0f;
    float acc = 0.f;
    for (int n = st; n < en; n++) {
        float w = __expf(g_s[n] - m) * inv;
        acc += w * g_h[n * 128 + t];
    }
    g_comb[g * 192 + t] = acc;
    if (t < 32)       g_comb[g * 192 + 128 + t]        = Eb0[brand0[g] * 32 + t];
    else if (t < 64)  g_comb[g * 192 + 160 + (t - 32)] = Eb1[brand1[g] * 32 + (t - 32)];
}

// --------------------------------- MLP head ---------------------------------
__global__ void mlp1_kernel(const float* __restrict__ P1w, const float* __restrict__ P1b) {
    int g = blockIdx.x;     // BB blocks
    int j = threadIdx.x;    // 256 threads
    __shared__ float cs[192];
    if (j < 192) cs[j] = g_comb[g * 192 + j];
    __syncthreads();
    float a = P1b[j];
    #pragma unroll 8
    for (int k = 0; k < 192; k++) a += cs[k] * P1w[k * 256 + j];
    g_z1p[g * 256 + j] = a;
}

__global__ void bnrelu1_kernel(const float* __restrict__ sc, const float* __restrict__ bi) {
    int j = blockIdx.x;     // 256 blocks (features)
    int t = threadIdx.x;    // 128 threads (rows)
    __shared__ float red[128];
    float x = g_z1p[t * 256 + j];
    red[t] = x; __syncthreads();
    for (int o = 64; o; o >>= 1) { if (t < o) red[t] += red[t + o]; __syncthreads(); }
    float mu = red[0] * (1.0f / 128.0f); __syncthreads();
    red[t] = x * x; __syncthreads();
    for (int o = 64; o; o >>= 1) { if (t < o) red[t] += red[t + o]; __syncthreads(); }
    float var = red[0] * (1.0f / 128.0f) - mu * mu;
    float v = (x - mu) * rsqrtf(var + 1e-5f) * sc[j] + bi[j];
    g_z1[t * 256 + j] = fmaxf(v, 0.0f);
}

__global__ void mlp2_kernel(const float* __restrict__ P2w, const float* __restrict__ P2b) {
    int g = blockIdx.x;     // BB blocks
    int j = threadIdx.x;    // 128 threads
    __shared__ float zs[256];
    zs[j]       = g_z1[g * 256 + j];
    zs[j + 128] = g_z1[g * 256 + j + 128];
    __syncthreads();
    float a = P2b[j];
    #pragma unroll 8
    for (int k = 0; k < 256; k++) a += zs[k] * P2w[k * 128 + j];
    g_z2p[g * 128 + j] = a;
}

__global__ void bnrelu2_kernel(const float* __restrict__ sc, const float* __restrict__ bi) {
    int j = blockIdx.x;     // 128 blocks
    int t = threadIdx.x;    // 128 threads
    __shared__ float red[128];
    float x = g_z2p[t * 128 + j];
    red[t] = x; __syncthreads();
    for (int o = 64; o; o >>= 1) { if (t < o) red[t] += red[t + o]; __syncthreads(); }
    float mu = red[0] * (1.0f / 128.0f); __syncthreads();
    red[t] = x * x; __syncthreads();
    for (int o = 64; o; o >>= 1) { if (t < o) red[t] += red[t + o]; __syncthreads(); }
    float var = red[0] * (1.0f / 128.0f) - mu * mu;
    float v = (x - mu) * rsqrtf(var + 1e-5f) * sc[j] + bi[j];
    g_z2[t * 128 + j] = fmaxf(v, 0.0f);
}

__global__ void final_kernel(const float* __restrict__ P3w,
                             const float* __restrict__ P3b,
                             float* __restrict__ out) {
    __shared__ float zs[16][128];
    int col = blockIdx.x * 256 + threadIdx.x;
    int r0  = blockIdx.y * 16;
    for (int i = threadIdx.x; i < 16 * 128; i += 256) {
        int r = i >> 7, k = i & 127;
        zs[r][k] = g_z2[(r0 + r) * 128 + k];
    }
    __syncthreads();
    if (col >= NGG) return;
    float acc[16];
    #pragma unroll
    for (int r = 0; r < 16; r++) acc[r] = 0.f;
    for (int k = 0; k < 128; k++) {
        float b = P3w[k * NGG + col];
        #pragma unroll
        for (int r = 0; r < 16; r++) acc[r] += zs[r][k] * b;
    }
    float add = P3b[col] + 0.1f * g_nodebias[col];
    #pragma unroll
    for (int r = 0; r < 16; r++) out[(r0 + r) * NGG + col] = acc[r] + add;
}

// ------------------------------- kernel_launch -------------------------------
extern "C" void kernel_launch(void* const* d_in, const int* in_sizes, int n_in,
                              void* d_out, int out_size) {
    const float* x        = (const float*)d_in[0];
    const int*   ei       = (const int*)  d_in[1];
    const int*   batch    = (const int*)  d_in[2];
    const int*   brand0   = (const int*)  d_in[3];
    const int*   brand1   = (const int*)  d_in[4];
    const float* Wg       = (const float*)d_in[5];
    const float* att_src  = (const float*)d_in[6];
    const float* att_dst  = (const float*)d_in[7];
    const float* gat_bias = (const float*)d_in[8];
    const float* bn_scale = (const float*)d_in[9];
    const float* bn_bias  = (const float*)d_in[10];
    const float* attA1    = (const float*)d_in[11];
    const float* attb1    = (const float*)d_in[12];
    const float* attA2    = (const float*)d_in[13];
    const float* attb2    = (const float*)d_in[14];
    const float* Eb0      = (const float*)d_in[15];
    const float* Eb1      = (const float*)d_in[16];
    const float* P1w      = (const float*)d_in[17];
    const float* P1b      = (const float*)d_in[18];
    const float* pbn1_s   = (const float*)d_in[19];
    const float* pbn1_b   = (const float*)d_in[20];
    const float* P2w      = (const float*)d_in[21];
    const float* P2b      = (const float*)d_in[22];
    const float* pbn2_s   = (const float*)d_in[23];
    const float* pbn2_b   = (const float*)d_in[24];
    const float* P3w      = (const float*)d_in[25];
    const float* P3b      = (const float*)d_in[26];
    const float* Gemb     = (const float*)d_in[27];
    float* out = (float*)d_out;

    float* d_xw = nullptr; cudaGetSymbolAddress((void**)&d_xw, g_xw);
    float* d_t  = nullptr; cudaGetSymbolAddress((void**)&d_t,  g_t);
    unsigned *d_wh = nullptr, *d_wl = nullptr, *d_a1h = nullptr, *d_a1l = nullptr;
    cudaGetSymbolAddress((void**)&d_wh,  g_Wnhi);
    cudaGetSymbolAddress((void**)&d_wl,  g_Wnlo);
    cudaGetSymbolAddress((void**)&d_a1h, g_A1hi);
    cudaGetSymbolAddress((void**)&d_a1l, g_A1lo);

    // setup
    init_kernel<<<(NN + 255) / 256, 256>>>();
    copy_h_kernel<<<(NN * 32 + 255) / 256, 256>>>((const float4*)x);
    nodebias_kernel<<<(NGG * 32 + 255) / 256, 256>>>(Gemb);
    hist_kernel<<<(ETOT + 255) / 256, 256>>>(ei);
    scan1_kernel<<<20, 1024>>>();
    scan2_kernel<<<1, 32>>>();
    scan3_kernel<<<(NN + 255) / 256, 256>>>();
    scatter_kernel<<<(ETOT + 255) / 256, 256>>>(ei);

    // GAT layers
    for (int l = 0; l < 3; l++) {
        transpose_w_kernel<<<(512 * 64 + 255) / 256, 256>>>(Wg, l);
        gemm_bf16_kernel<512><<<dim3(8, (NN + 127) / 128), 256>>>(d_wh, d_wl, d_xw);
        att_coef_kernel<<<256, 256>>>(att_src + l * 512, att_dst + l * 512);
        aggregate_kernel<<<512, 256>>>(gat_bias + l * 128);
        bn_finalize_kernel<<<1, 128>>>();
        bn_apply_kernel<<<(NN * 32 + 255) / 256, 256>>>(bn_scale + l * 128,
                                                        bn_bias + l * 128,
                                                        l > 0 ? 1 : 0);
    }

    // attention pooling
    a1prep_kernel<<<(256 * 64 + 255) / 256, 256>>>(attA1);
    gemm_bf16_kernel<256><<<dim3(4, (NN + 127) / 128), 256>>>(d_a1h, d_a1l, d_t);
    score_kernel<<<(NN * 32 + 255) / 256, 256>>>(attb1, attA2, attb2);
    bounds_kernel<<<(NN + 255) / 256, 256>>>(batch);
    pool_kernel<<<BB, 128>>>(brand0, brand1, Eb0, Eb1);

    // MLP head
    mlp1_kernel<<<BB, 256>>>(P1w, P1b);
    bnrelu1_kernel<<<256, 128>>>(pbn1_s, pbn1_b);
    mlp2_kernel<<<BB, 128>>>(P2w, P2b);
    bnrelu2_kernel<<<128, 128>>>(pbn2_s, pbn2_b);
    final_kernel<<<dim3((NGG + 255) / 256, 8), 256>>>(P3w, P3b, out);
}

// round 5
// speedup vs baseline: 1.7865x; 1.4453x over previous
#include <cuda_runtime.h>
#include <cuda_bf16.h>
#include <math.h>

// Problem constants
#define NN   20000      // nodes
#define EE   160000     // edges (without self loops)
#define ETOT 180000     // edges + self loops
#define BB   128        // graphs
#define NGG  10000

// ------------------------- scratch (device globals) -------------------------
__device__ float    g_h   [NN * 128];   // current node features
__device__ unsigned g_hhi [NN * 64];    // h split hi (2 bf16 per uint)
__device__ unsigned g_hlo [NN * 64];    // h split lo
__device__ float    g_xw  [NN * 512];   // h @ W  -> (n, h, o)
__device__ float    g_t   [NN * 256];   // h @ attA1
__device__ float    g_hn  [NN * 128];   // pre-BN layer output
__device__ float    g_es  [NN * 4];
__device__ float    g_ed  [NN * 4];
__device__ unsigned g_Wnhi[3 * 512 * 64];   // W as [l][h*128+o][f-word], bf16 hi
__device__ unsigned g_Wnlo[3 * 512 * 64];
__device__ unsigned g_A1hi[256 * 64];   // attA1 as [n][k], bf16 hi packed
__device__ unsigned g_A1lo[256 * 64];
__device__ float    g_wa  [3 * 8 * 128];    // [l][h*2+sd][f] = W @ a
__device__ int   g_deg [NN];
__device__ int   g_off [NN + 1];
__device__ int   g_cur [NN];
__device__ int   g_csr [ETOT];
__device__ int   g_bsum[20];
__device__ int   g_bpre[20];
__device__ float g_bnsum[128];
__device__ float g_bnsq [128];
__device__ float g_s   [NN];
__device__ int   g_gstart[BB];
__device__ int   g_gend  [BB];
__device__ float g_comb[BB * 192];
__device__ float g_z1p [BB * 256];
__device__ float g_z1  [BB * 256];
__device__ float g_z2p [BB * 128];
__device__ float g_z2  [BB * 128];
__device__ float g_nodebias[NGG];

// --------------------------- bf16 split helper -------------------------------
__device__ __forceinline__ void split2(float x, float y, unsigned& hi, unsigned& lo) {
    __nv_bfloat16 hx = __float2bfloat16_rn(x);
    __nv_bfloat16 hy = __float2bfloat16_rn(y);
    float rx = x - __bfloat162float(hx);
    float ry = y - __bfloat162float(hy);
    __nv_bfloat16 lx = __float2bfloat16_rn(rx);
    __nv_bfloat16 ly = __float2bfloat16_rn(ry);
    hi = (unsigned)__bfloat16_as_ushort(hx) | ((unsigned)__bfloat16_as_ushort(hy) << 16);
    lo = (unsigned)__bfloat16_as_ushort(lx) | ((unsigned)__bfloat16_as_ushort(ly) << 16);
}

// ------------------------------- setup kernels -------------------------------
__global__ void init_kernel() {
    int i = blockIdx.x * blockDim.x + threadIdx.x;
    if (i < NN) g_deg[i] = 0;
    if (i < BB) { g_gstart[i] = NN; g_gend[i] = 0; }
}

__global__ void copy_h_kernel(const float4* __restrict__ x) {
    int i = blockIdx.x * blockDim.x + threadIdx.x;
    if (i >= NN * 32) return;
    float4 v = x[i];
    ((float4*)g_h)[i] = v;
    uint2 hi, lo;
    split2(v.x, v.y, hi.x, lo.x);
    split2(v.z, v.w, hi.y, lo.y);
    ((uint2*)g_hhi)[i] = hi;
    ((uint2*)g_hlo)[i] = lo;
}

__global__ void nodebias_kernel(const float* __restrict__ Gemb) {
    int gid  = blockIdx.x * blockDim.x + threadIdx.x;
    int w    = gid >> 5;
    int lane = gid & 31;
    if (w >= NGG) return;
    float v = Gemb[w * 64 + lane] + Gemb[w * 64 + 32 + lane];
    #pragma unroll
    for (int o = 16; o; o >>= 1) v += __shfl_xor_sync(0xffffffffu, v, o);
    if (lane == 0) g_nodebias[w] = v * (1.0f / 64.0f);
}

__global__ void hist_kernel(const int* __restrict__ ei) {
    int e = blockIdx.x * blockDim.x + threadIdx.x;
    if (e >= ETOT) return;
    int dst = (e < EE) ? ei[EE + e] : (e - EE);
    atomicAdd(&g_deg[dst], 1);
}

__global__ void scan1_kernel() {   // 20 blocks x 1024
    __shared__ int sh[1024];
    int b = blockIdx.x, t = threadIdx.x;
    int i = b * 1024 + t;
    int v = (i < NN) ? g_deg[i] : 0;
    sh[t] = v;
    __syncthreads();
    for (int o = 1; o < 1024; o <<= 1) {
        int xv = (t >= o) ? sh[t - o] : 0;
        __syncthreads();
        sh[t] += xv;
        __syncthreads();
    }
    if (i < NN) g_off[i] = sh[t] - v;
    if (t == 1023) g_bsum[b] = sh[1023];
}

__global__ void scan2_kernel() {   // 1 block, 32 threads
    int t = threadIdx.x;
    int v = (t < 20) ? g_bsum[t] : 0;
    #pragma unroll
    for (int o = 1; o < 32; o <<= 1) {
        int xv = __shfl_up_sync(0xffffffffu, v, o);
        if (t >= o) v += xv;
    }
    if (t < 20) g_bpre[t] = v - g_bsum[t];
    if (t == 19) g_off[NN] = v;
}

__global__ void scan3_kernel() {
    int i = blockIdx.x * blockDim.x + threadIdx.x;
    if (i >= NN) return;
    int val = g_off[i] + g_bpre[i >> 10];
    g_off[i] = val;
    g_cur[i] = val;
}

__global__ void scatter_kernel(const int* __restrict__ ei) {
    int e = blockIdx.x * blockDim.x + threadIdx.x;
    if (e >= ETOT) return;
    int src, dst;
    if (e < EE) { src = ei[e]; dst = ei[EE + e]; }
    else        { src = e - EE; dst = e - EE; }
    int pos = atomicAdd(&g_cur[dst], 1);
    g_csr[pos] = src;
}

// ------------------- weight prep: all 3 layers at once -----------------------
__global__ void transpose_w3_kernel(const float* __restrict__ Wg) {
    int idx = blockIdx.x * blockDim.x + threadIdx.x;   // 3*512*64
    if (idx >= 3 * 512 * 64) return;
    int l  = idx >> 15;
    int r  = idx & 32767;
    int hn = r >> 6;            // h*128 + o
    int f  = (r & 63) * 2;
    int h = hn >> 7, o = hn & 127;
    const float* base = Wg + ((l * 4 + h) * 128) * 128 + o;
    float v0 = base[f * 128];
    float v1 = base[(f + 1) * 128];
    unsigned hi, lo;
    split2(v0, v1, hi, lo);
    g_Wnhi[idx] = hi;
    g_Wnlo[idx] = lo;
}

// wa[l][h*2+sd][f] = sum_o W[l,h,f,o] * a_{src|dst}[l,h,o]
__global__ void wa_prep_kernel(const float* __restrict__ Wg,
                               const float* __restrict__ asrc,
                               const float* __restrict__ adst) {
    int idx = blockIdx.x * blockDim.x + threadIdx.x;   // 3*8*128
    if (idx >= 3 * 8 * 128) return;
    int l = idx >> 10;
    int t = (idx >> 7) & 7;
    int f = idx & 127;
    int h = t >> 1, sd = t & 1;
    const float* a = (sd ? adst : asrc) + (l * 4 + h) * 128;
    const float* w = Wg + (((l * 4 + h) * 128) + f) * 128;
    float s = 0.f;
    #pragma unroll 4
    for (int o = 0; o < 128; o++) s += w[o] * a[o];
    g_wa[idx] = s;
}

// attA1 (128 x 256) -> [n][k] bf16 hi/lo
__global__ void a1prep_kernel(const float* __restrict__ attA1) {
    int idx = blockIdx.x * blockDim.x + threadIdx.x;   // 256*64
    if (idx >= 256 * 64) return;
    int n = idx >> 6;
    int k = (idx & 63) * 2;
    float v0 = attA1[k * 256 + n];
    float v1 = attA1[(k + 1) * 256 + n];
    unsigned hi, lo;
    split2(v0, v1, hi, lo);
    g_A1hi[idx] = hi;
    g_A1lo[idx] = lo;
}

// ---------------- BF16 tensor-core GEMM (ldmatrix, 3x split) -----------------
#define LDMX4(r, addr)                                                         \
    asm volatile("ldmatrix.sync.aligned.m8n8.x4.shared.b16 {%0,%1,%2,%3}, [%4];" \
                 : "=r"(r[0]), "=r"(r[1]), "=r"(r[2]), "=r"(r[3]) : "r"(addr))

#define MMA_BF16(c, a, b0, b1)                                                 \
    asm volatile("mma.sync.aligned.m16n8k16.row.col.f32.bf16.bf16.f32 "        \
                 "{%0,%1,%2,%3}, {%4,%5,%6,%7}, {%8,%9}, {%0,%1,%2,%3};"       \
                 : "+f"(c[0]), "+f"(c[1]), "+f"(c[2]), "+f"(c[3])              \
                 : "r"(a[0]), "r"(a[1]), "r"(a[2]), "r"(a[3]), "r"(b0), "r"(b1))

#define GEMM_SMEM_BYTES ((2 * 128 * 68 + 2 * 64 * 68) * 4)

template <int NC>
__global__ __launch_bounds__(256) void gemm_ldm_kernel(
        const unsigned* __restrict__ Bhi, const unsigned* __restrict__ Blo,
        float* __restrict__ C) {
    extern __shared__ unsigned sm[];
    unsigned* sAh = sm;                        // [128][68]
    unsigned* sAl = sAh + 128 * 68;
    unsigned* sBh = sAl + 128 * 68;            // [64][68]
    unsigned* sBl = sBh + 64 * 68;

    int tid  = threadIdx.x;
    int row0 = blockIdx.y * 128;
    int col0 = blockIdx.x * 64;

    for (int i = tid; i < 2048; i += 256) {
        int r = i >> 4, q = (i & 15) << 2;
        uint4 vh = make_uint4(0, 0, 0, 0), vl = make_uint4(0, 0, 0, 0);
        if (row0 + r < NN) {
            vh = *(const uint4*)&g_hhi[(row0 + r) * 64 + q];
            vl = *(const uint4*)&g_hlo[(row0 + r) * 64 + q];
        }
        *(uint4*)&sAh[r * 68 + q] = vh;
        *(uint4*)&sAl[r * 68 + q] = vl;
    }
    for (int i = tid; i < 1024; i += 256) {
        int n = i >> 4, q = (i & 15) << 2;
        *(uint4*)&sBh[n * 68 + q] = *(const uint4*)&Bhi[(col0 + n) * 64 + q];
        *(uint4*)&sBl[n * 68 + q] = *(const uint4*)&Blo[(col0 + n) * 64 + q];
    }
    __syncthreads();

    int lane = tid & 31, warp = tid >> 5;
    int arow  = warp * 16 + (lane & 15);
    int akoff = (lane & 16) ? 4 : 0;
    unsigned aAh = (unsigned)__cvta_generic_to_shared(&sAh[arow * 68 + akoff]);
    unsigned aAl = (unsigned)__cvta_generic_to_shared(&sAl[arow * 68 + akoff]);
    int bnr   = (lane & 7) + ((lane & 16) ? 8 : 0);
    int bkoff = (lane & 8) ? 4 : 0;
    unsigned aBh[4], aBl[4];
    #pragma unroll
    for (int p = 0; p < 4; p++) {
        aBh[p] = (unsigned)__cvta_generic_to_shared(&sBh[(p * 16 + bnr) * 68 + bkoff]);
        aBl[p] = (unsigned)__cvta_generic_to_shared(&sBl[(p * 16 + bnr) * 68 + bkoff]);
    }

    float acc[8][4];
    #pragma unroll
    for (int nt = 0; nt < 8; nt++)
        #pragma unroll
        for (int i = 0; i < 4; i++) acc[nt][i] = 0.0f;

    #pragma unroll
    for (int kc = 0; kc < 8; kc++) {
        unsigned koff = kc * 32;
        unsigned ah[4], al[4];
        LDMX4(ah, aAh + koff);
        LDMX4(al, aAl + koff);
        #pragma unroll
        for (int p = 0; p < 4; p++) {
            unsigned bh[4], bl[4];
            LDMX4(bh, aBh[p] + koff);
            LDMX4(bl, aBl[p] + koff);
            MMA_BF16(acc[2 * p],     ah, bh[0], bh[1]);
            MMA_BF16(acc[2 * p],     ah, bl[0], bl[1]);
            MMA_BF16(acc[2 * p],     al, bh[0], bh[1]);
            MMA_BF16(acc[2 * p + 1], ah, bh[2], bh[3]);
            MMA_BF16(acc[2 * p + 1], ah, bl[2], bl[3]);
            MMA_BF16(acc[2 * p + 1], al, bh[2], bh[3]);
        }
    }

    int gid = lane >> 2, tq = lane & 3;
    int ra = row0 + warp * 16 + gid;
    int rb = ra + 8;
    #pragma unroll
    for (int nt = 0; nt < 8; nt++) {
        int cc = col0 + nt * 8 + tq * 2;
        if (ra < NN) *(float2*)&C[ra * NC + cc] = make_float2(acc[nt][0], acc[nt][1]);
        if (rb < NN) *(float2*)&C[rb * NC + cc] = make_float2(acc[nt][2], acc[nt][3]);
    }
}

// ------------------------- es/ed from h . (W@a) ------------------------------
__global__ void escoef_kernel(int l) {
    __shared__ float swa[8 * 128];
    int tid = threadIdx.x;   // 256
    for (int i = tid; i < 1024; i += 256) swa[i] = g_wa[l * 1024 + i];
    if (blockIdx.x == 0 && tid < 128) { g_bnsum[tid] = 0.f; g_bnsq[tid] = 0.f; }
    __syncthreads();
    int warp = tid >> 5, lane = tid & 31;
    int n = blockIdx.x * 8 + warp;
    if (n >= NN) return;
    float4 hv = *(const float4*)&g_h[n * 128 + lane * 4];
    #pragma unroll
    for (int t = 0; t < 8; t++) {
        float4 w4 = *(const float4*)&swa[t * 128 + lane * 4];
        float d = hv.x * w4.x + hv.y * w4.y + hv.z * w4.z + hv.w * w4.w;
        #pragma unroll
        for (int o = 16; o; o >>= 1) d += __shfl_xor_sync(0xffffffffu, d, o);
        if (lane == 0) {
            int h = t >> 1;
            if (t & 1) g_ed[n * 4 + h] = d;
            else       g_es[n * 4 + h] = d;
        }
    }
}

__device__ __forceinline__ float lrelu(float v) {
    return v > 0.f ? v : 0.2f * v;
}

__global__ void aggregate_kernel(const float* __restrict__ gbias) {
    __shared__ float ssum[128], ssq[128];
    int tid  = threadIdx.x;
    if (tid < 128) { ssum[tid] = 0.f; ssq[tid] = 0.f; }
    __syncthreads();
    int gt   = blockIdx.x * blockDim.x + tid;
    int warp = gt >> 5;
    int lane = gt & 31;
    int nw = (gridDim.x * blockDim.x) >> 5;
    float4 csum = make_float4(0.f, 0.f, 0.f, 0.f);
    float4 csq  = make_float4(0.f, 0.f, 0.f, 0.f);
    float4 gb = ((const float4*)gbias)[lane];
    for (int n = warp; n < NN; n += nw) {
        int o0 = g_off[n], o1 = g_off[n + 1];
        float4 edn = *(const float4*)&g_ed[n * 4];

        float m0 = -1e30f, m1 = -1e30f, m2 = -1e30f, m3 = -1e30f;
        for (int e = o0 + lane; e < o1; e += 32) {
            int s = g_csr[e];
            float4 es = *(const float4*)&g_es[s * 4];
            m0 = fmaxf(m0, lrelu(es.x + edn.x));
            m1 = fmaxf(m1, lrelu(es.y + edn.y));
            m2 = fmaxf(m2, lrelu(es.z + edn.z));
            m3 = fmaxf(m3, lrelu(es.w + edn.w));
        }
        #pragma unroll
        for (int o = 16; o; o >>= 1) {
            m0 = fmaxf(m0, __shfl_xor_sync(0xffffffffu, m0, o));
            m1 = fmaxf(m1, __shfl_xor_sync(0xffffffffu, m1, o));
            m2 = fmaxf(m2, __shfl_xor_sync(0xffffffffu, m2, o));
            m3 = fmaxf(m3, __shfl_xor_sync(0xffffffffu, m3, o));
        }

        float den[4] = {0.f, 0.f, 0.f, 0.f};
        float4 acc[4];
        #pragma unroll
        for (int h = 0; h < 4; h++) acc[h] = make_float4(0.f, 0.f, 0.f, 0.f);

        for (int e = o0; e < o1; e++) {
            int s = g_csr[e];
            float4 es = *(const float4*)&g_es[s * 4];
            float w0 = __expf(lrelu(es.x + edn.x) - m0);
            float w1 = __expf(lrelu(es.y + edn.y) - m1);
            float w2 = __expf(lrelu(es.z + edn.z) - m2);
            float w3 = __expf(lrelu(es.w + edn.w) - m3);
            den[0] += w0; den[1] += w1; den[2] += w2; den[3] += w3;
            const float4* xp = (const float4*)&g_xw[s * 512];
            float wv[4] = {w0, w1, w2, w3};
            #pragma unroll
            for (int h = 0; h < 4; h++) {
                float4 xv = xp[h * 32 + lane];
                acc[h].x += wv[h] * xv.x;
                acc[h].y += wv[h] * xv.y;
                acc[h].z += wv[h] * xv.z;
                acc[h].w += wv[h] * xv.w;
            }
        }

        float i0 = 1.f / den[0], i1 = 1.f / den[1], i2 = 1.f / den[2], i3 = 1.f / den[3];
        float4 v;
        v.x = (acc[0].x * i0 + acc[1].x * i1 + acc[2].x * i2 + acc[3].x * i3) * 0.25f + gb.x;
        v.y = (acc[0].y * i0 + acc[1].y * i1 + acc[2].y * i2 + acc[3].y * i3) * 0.25f + gb.y;
        v.z = (acc[0].z * i0 + acc[1].z * i1 + acc[2].z * i2 + acc[3].z * i3) * 0.25f + gb.z;
        v.w = (acc[0].w * i0 + acc[1].w * i1 + acc[2].w * i2 + acc[3].w * i3) * 0.25f + gb.w;
        *(float4*)&g_hn[n * 128 + lane * 4] = v;
        csum.x += v.x; csum.y += v.y; csum.z += v.z; csum.w += v.w;
        csq.x += v.x * v.x; csq.y += v.y * v.y; csq.z += v.z * v.z; csq.w += v.w * v.w;
    }
    atomicAdd(&ssum[lane * 4 + 0], csum.x);
    atomicAdd(&ssum[lane * 4 + 1], csum.y);
    atomicAdd(&ssum[lane * 4 + 2], csum.z);
    atomicAdd(&ssum[lane * 4 + 3], csum.w);
    atomicAdd(&ssq[lane * 4 + 0], csq.x);
    atomicAdd(&ssq[lane * 4 + 1], csq.y);
    atomicAdd(&ssq[lane * 4 + 2], csq.z);
    atomicAdd(&ssq[lane * 4 + 3], csq.w);
    __syncthreads();
    if (tid < 128) {
        atomicAdd(&g_bnsum[tid], ssum[tid]);
        atomicAdd(&g_bnsq[tid],  ssq[tid]);
    }
}

__global__ void bn_apply_kernel(const float* __restrict__ scale,
                                const float* __restrict__ bias, int addRes) {
    __shared__ float sinv[128], soff[128];
    int tid = threadIdx.x;
    if (tid < 128) {
        float mu  = g_bnsum[tid] * (1.0f / NN);
        float var = g_bnsq[tid] * (1.0f / NN) - mu * mu;
        float iv  = rsqrtf(var + 1e-5f) * scale[tid];
        sinv[tid] = iv;
        soff[tid] = bias[tid] - mu * iv;
    }
    __syncthreads();
    int idx = blockIdx.x * blockDim.x + tid;
    if (idx >= NN * 32) return;
    int c4 = (idx & 31) * 4;
    float4 v = ((const float4*)g_hn)[idx];
    float4 r;
    r.x = fmaxf(v.x * sinv[c4 + 0] + soff[c4 + 0], 0.f);
    r.y = fmaxf(v.y * sinv[c4 + 1] + soff[c4 + 1], 0.f);
    r.z = fmaxf(v.z * sinv[c4 + 2] + soff[c4 + 2], 0.f);
    r.w = fmaxf(v.w * sinv[c4 + 3] + soff[c4 + 3], 0.f);
    if (addRes) {
        float4 h = ((const float4*)g_h)[idx];
        r.x += h.x; r.y += h.y; r.z += h.z; r.w += h.w;
    }
    ((float4*)g_h)[idx] = r;
    uint2 hi, lo;
    split2(r.x, r.y, hi.x, lo.x);
    split2(r.z, r.w, hi.y, lo.y);
    ((uint2*)g_hhi)[idx] = hi;
    ((uint2*)g_hlo)[idx] = lo;
}

// ------------------------------- pooling head -------------------------------
__global__ void score_kernel(const float* __restrict__ ab1,
                             const float* __restrict__ aA2,
                             const float* __restrict__ ab2) {
    int gt   = blockIdx.x * blockDim.x + threadIdx.x;
    int w    = gt >> 5;
    int lane = gt & 31;
    if (w >= NN) return;
    float acc = 0.f;
    #pragma unroll
    for (int j = lane; j < 256; j += 32)
        acc += tanhf(g_t[w * 256 + j] + ab1[j]) * aA2[j];
    #pragma unroll
    for (int o = 16; o; o >>= 1) acc += __shfl_xor_sync(0xffffffffu, acc, o);
    if (lane == 0) g_s[w] = acc + ab2[0];
}

__global__ void bounds_kernel(const int* __restrict__ batch) {
    int n = blockIdx.x * blockDim.x + threadIdx.x;
    if (n >= NN) return;
    int g = batch[n];
    atomicMin(&g_gstart[g], n);
    atomicMax(&g_gend[g], n + 1);
}

__global__ void pool_kernel(const int* __restrict__ brand0,
                            const int* __restrict__ brand1,
                            const float* __restrict__ Eb0,
                            const float* __restrict__ Eb1) {
    int g = blockIdx.x;
    int t = threadIdx.x;    // 128
    __shared__ float red[128];
    int st = g_gstart[g], en = g_gend[g];

    float m = -1e30f;
    for (int n = st + t; n < en; n += 128) m = fmaxf(m, g_s[n]);
    red[t] = m; __syncthreads();
    for (int o = 64; o; o >>= 1) { if (t < o) red[t] = fmaxf(red[t], red[t + o]); __syncthreads(); }
    m = red[0]; __syncthreads();

    float d = 0.f;
    for (int n = st + t; n < en; n += 128) d += __expf(g_s[n] - m);
    red[t] = d; __syncthreads();
    for (int o = 64; o; o >>= 1) { if (t < o) red[t] += red[t + o]; __syncthreads(); }
    d = red[0]; __syncthreads();

    float inv = (en > st) ? 1.0f / d : 0.0f;
    float acc = 0.f;
    for (int n = st; n < en; n++) {
        float w = __expf(g_s[n] - m) * inv;
        acc += w * g_h[n * 128 + t];
    }
    g_comb[g * 192 + t] = acc;
    if (t < 32)       g_comb[g * 192 + 128 + t]        = Eb0[brand0[g] * 32 + t];
    else if (t < 64)  g_comb[g * 192 + 160 + (t - 32)] = Eb1[brand1[g] * 32 + (t - 32)];
}

// --------------------------------- MLP head ---------------------------------
__global__ void mlp1_kernel(const float* __restrict__ P1w, const float* __restrict__ P1b) {
    int g = blockIdx.x;
    int j = threadIdx.x;    // 256
    __shared__ float cs[192];
    if (j < 192) cs[j] = g_comb[g * 192 + j];
    __syncthreads();
    float a = P1b[j];
    #pragma unroll 8
    for (int k = 0; k < 192; k++) a += cs[k] * P1w[k * 256 + j];
    g_z1p[g * 256 + j] = a;
}

__global__ void bnrelu1_kernel(const float* __restrict__ sc, const float* __restrict__ bi) {
    int j = blockIdx.x;     // 256 blocks
    int t = threadIdx.x;    // 128 threads
    __shared__ float red[128];
    float x = g_z1p[t * 256 + j];
    red[t] = x; __syncthreads();
    for (int o = 64; o; o >>= 1) { if (t < o) red[t] += red[t + o]; __syncthreads(); }
    float mu = red[0] * (1.0f / 128.0f); __syncthreads();
    red[t] = x * x; __syncthreads();
    for (int o = 64; o; o >>= 1) { if (t < o) red[t] += red[t + o]; __syncthreads(); }
    float var = red[0] * (1.0f / 128.0f) - mu * mu;
    float v = (x - mu) * rsqrtf(var + 1e-5f) * sc[j] + bi[j];
    g_z1[t * 256 + j] = fmaxf(v, 0.0f);
}

__global__ void mlp2_kernel(const float* __restrict__ P2w, const float* __restrict__ P2b) {
    int g = blockIdx.x;
    int j = threadIdx.x;    // 128
    __shared__ float zs[256];
    zs[j]       = g_z1[g * 256 + j];
    zs[j + 128] = g_z1[g * 256 + j + 128];
    __syncthreads();
    float a = P2b[j];
    #pragma unroll 8
    for (int k = 0; k < 256; k++) a += zs[k] * P2w[k * 128 + j];
    g_z2p[g * 128 + j] = a;
}

__global__ void bnrelu2_kernel(const float* __restrict__ sc, const float* __restrict__ bi) {
    int j = blockIdx.x;     // 128 blocks
    int t = threadIdx.x;    // 128 threads
    __shared__ float red[128];
    float x = g_z2p[t * 128 + j];
    red[t] = x; __syncthreads();
    for (int o = 64; o; o >>= 1) { if (t < o) red[t] += red[t + o]; __syncthreads(); }
    float mu = red[0] * (1.0f / 128.0f); __syncthreads();
    red[t] = x * x; __syncthreads();
    for (int o = 64; o; o >>= 1) { if (t < o) red[t] += red[t + o]; __syncthreads(); }
    float var = red[0] * (1.0f / 128.0f) - mu * mu;
    float v = (x - mu) * rsqrtf(var + 1e-5f) * sc[j] + bi[j];
    g_z2[t * 128 + j] = fmaxf(v, 0.0f);
}

__global__ void final_kernel(const float* __restrict__ P3w,
                             const float* __restrict__ P3b,
                             float* __restrict__ out) {
    __shared__ float zs[16][128];
    int col = blockIdx.x * 256 + threadIdx.x;
    int r0  = blockIdx.y * 16;
    for (int i = threadIdx.x; i < 16 * 128; i += 256) {
        int r = i >> 7, k = i & 127;
        zs[r][k] = g_z2[(r0 + r) * 128 + k];
    }
    __syncthreads();
    if (col >= NGG) return;
    float acc[16];
    #pragma unroll
    for (int r = 0; r < 16; r++) acc[r] = 0.f;
    for (int k = 0; k < 128; k++) {
        float b = P3w[k * NGG + col];
        #pragma unroll
        for (int r = 0; r < 16; r++) acc[r] += zs[r][k] * b;
    }
    float add = P3b[col] + 0.1f * g_nodebias[col];
    #pragma unroll
    for (int r = 0; r < 16; r++) out[(r0 + r) * NGG + col] = acc[r] + add;
}

// ------------------------------- kernel_launch -------------------------------
extern "C" void kernel_launch(void* const* d_in, const int* in_sizes, int n_in,
                              void* d_out, int out_size) {
    const float* x        = (const float*)d_in[0];
    const int*   ei       = (const int*)  d_in[1];
    const int*   batch    = (const int*)  d_in[2];
    const int*   brand0   = (const int*)  d_in[3];
    const int*   brand1   = (const int*)  d_in[4];
    const float* Wg       = (const float*)d_in[5];
    const float* att_src  = (const float*)d_in[6];
    const float* att_dst  = (const float*)d_in[7];
    const float* gat_bias = (const float*)d_in[8];
    const float* bn_scale = (const float*)d_in[9];
    const float* bn_bias  = (const float*)d_in[10];
    const float* attA1    = (const float*)d_in[11];
    const float* attb1    = (const float*)d_in[12];
    const float* attA2    = (const float*)d_in[13];
    const float* attb2    = (const float*)d_in[14];
    const float* Eb0      = (const float*)d_in[15];
    const float* Eb1      = (const float*)d_in[16];
    const float* P1w      = (const float*)d_in[17];
    const float* P1b      = (const float*)d_in[18];
    const float* pbn1_s   = (const float*)d_in[19];
    const float* pbn1_b   = (const float*)d_in[20];
    const float* P2w      = (const float*)d_in[21];
    const float* P2b      = (const float*)d_in[22];
    const float* pbn2_s   = (const float*)d_in[23];
    const float* pbn2_b   = (const float*)d_in[24];
    const float* P3w      = (const float*)d_in[25];
    const float* P3b      = (const float*)d_in[26];
    const float* Gemb     = (const float*)d_in[27];
    float* out = (float*)d_out;

    float* d_xw = nullptr; cudaGetSymbolAddress((void**)&d_xw, g_xw);
    float* d_t  = nullptr; cudaGetSymbolAddress((void**)&d_t,  g_t);
    unsigned *d_wh = nullptr, *d_wl = nullptr, *d_a1h = nullptr, *d_a1l = nullptr;
    cudaGetSymbolAddress((void**)&d_wh,  g_Wnhi);
    cudaGetSymbolAddress((void**)&d_wl,  g_Wnlo);
    cudaGetSymbolAddress((void**)&d_a1h, g_A1hi);
    cudaGetSymbolAddress((void**)&d_a1l, g_A1lo);

    cudaFuncSetAttribute(gemm_ldm_kernel<512>,
                         cudaFuncAttributeMaxDynamicSharedMemorySize, GEMM_SMEM_BYTES);
    cudaFuncSetAttribute(gemm_ldm_kernel<256>,
                         cudaFuncAttributeMaxDynamicSharedMemorySize, GEMM_SMEM_BYTES);

    // setup
    init_kernel<<<(NN + 255) / 256, 256>>>();
    copy_h_kernel<<<(NN * 32 + 255) / 256, 256>>>((const float4*)x);
    nodebias_kernel<<<(NGG * 32 + 255) / 256, 256>>>(Gemb);
    hist_kernel<<<(ETOT + 255) / 256, 256>>>(ei);
    scan1_kernel<<<20, 1024>>>();
    scan2_kernel<<<1, 32>>>();
    scan3_kernel<<<(NN + 255) / 256, 256>>>();
    scatter_kernel<<<(ETOT + 255) / 256, 256>>>(ei);
    transpose_w3_kernel<<<(3 * 512 * 64 + 255) / 256, 256>>>(Wg);
    wa_prep_kernel<<<(3 * 8 * 128 + 255) / 256, 256>>>(Wg, att_src, att_dst);
    a1prep_kernel<<<(256 * 64 + 255) / 256, 256>>>(attA1);

    // GAT layers
    for (int l = 0; l < 3; l++) {
        gemm_ldm_kernel<512><<<dim3(8, (NN + 127) / 128), 256, GEMM_SMEM_BYTES>>>(
            d_wh + l * 32768, d_wl + l * 32768, d_xw);
        escoef_kernel<<<(NN + 7) / 8, 256>>>(l);
        aggregate_kernel<<<512, 256>>>(gat_bias + l * 128);
        bn_apply_kernel<<<(NN * 32 + 255) / 256, 256>>>(bn_scale + l * 128,
                                                        bn_bias + l * 128,
                                                        l > 0 ? 1 : 0);
    }

    // attention pooling
    gemm_ldm_kernel<256><<<dim3(4, (NN + 127) / 128), 256, GEMM_SMEM_BYTES>>>(
        d_a1h, d_a1l, d_t);
    score_kernel<<<(NN * 32 + 255) / 256, 256>>>(attb1, attA2, attb2);
    bounds_kernel<<<(NN + 255) / 256, 256>>>(batch);
    pool_kernel<<<BB, 128>>>(brand0, brand1, Eb0, Eb1);

    // MLP head
    mlp1_kernel<<<BB, 256>>>(P1w, P1b);
    bnrelu1_kernel<<<256, 128>>>(pbn1_s, pbn1_b);
    mlp2_kernel<<<BB, 128>>>(P2w, P2b);
    bnrelu2_kernel<<<128, 128>>>(pbn2_s, pbn2_b);
    final_kernel<<<dim3((NGG + 255) / 256, 8), 256>>>(P3w, P3b, out);
}

// round 6
// speedup vs baseline: 2.1376x; 1.1965x over previous
#include <cuda_runtime.h>
#include <cuda_bf16.h>
#include <math.h>

// Problem constants
#define NN   20000      // nodes
#define EE   160000     // edges (without self loops)
#define ETOT 180000     // edges + self loops
#define BB   128        // graphs
#define NGG  10000

// ------------------------- scratch (device globals) -------------------------
__device__ float    g_h   [NN * 128];   // current node features
__device__ unsigned g_hhi [NN * 64];    // h split hi (2 bf16 per uint)
__device__ unsigned g_hlo [NN * 64];    // h split lo
__device__ float    g_xw  [NN * 512];   // h @ W  -> (n, h, o)
__device__ float    g_t   [NN * 256];   // h @ attA1
__device__ float    g_hn  [NN * 128];   // pre-BN layer output
__device__ float    g_es  [NN * 4];
__device__ float    g_ed  [NN * 4];
__device__ unsigned g_Wnhi[3 * 512 * 64];   // W as [l][h*128+o][f-word], bf16 hi
__device__ unsigned g_Wnlo[3 * 512 * 64];
__device__ unsigned g_A1hi[256 * 64];   // attA1 as [n][k], bf16 hi packed
__device__ unsigned g_A1lo[256 * 64];
__device__ float    g_wa  [3 * 8 * 128];    // [l][h*2+sd][f] = W @ a
__device__ int   g_deg [NN];
__device__ int   g_off [NN + 1];
__device__ int   g_cur [NN];
__device__ int   g_csr [ETOT];
__device__ int   g_bsum[20];
__device__ int   g_bpre[20];
__device__ float g_bnsum[3 * 128];
__device__ float g_bnsq [3 * 128];
__device__ float g_s   [NN];
__device__ int   g_gstart[BB];
__device__ int   g_gend  [BB];
__device__ float g_comb[BB * 192];
__device__ float g_z1p [BB * 256];
__device__ float g_z1  [BB * 256];
__device__ float g_z2p [BB * 128];
__device__ float g_z2  [BB * 128];
__device__ float g_nodebias[NGG];

// --------------------------- bf16 split helper -------------------------------
__device__ __forceinline__ void split2(float x, float y, unsigned& hi, unsigned& lo) {
    __nv_bfloat16 hx = __float2bfloat16_rn(x);
    __nv_bfloat16 hy = __float2bfloat16_rn(y);
    float rx = x - __bfloat162float(hx);
    float ry = y - __bfloat162float(hy);
    __nv_bfloat16 lx = __float2bfloat16_rn(rx);
    __nv_bfloat16 ly = __float2bfloat16_rn(ry);
    hi = (unsigned)__bfloat16_as_ushort(hx) | ((unsigned)__bfloat16_as_ushort(hy) << 16);
    lo = (unsigned)__bfloat16_as_ushort(lx) | ((unsigned)__bfloat16_as_ushort(ly) << 16);
}

// warp computes es/ed for its node from the float4 this lane holds
__device__ __forceinline__ void warp_esed(float4 v, int lane, int n, const float* wa) {
    int c4 = lane * 4;
    #pragma unroll
    for (int t = 0; t < 8; t++) {
        float4 w4 = *(const float4*)&wa[t * 128 + c4];
        float d = v.x * w4.x + v.y * w4.y + v.z * w4.z + v.w * w4.w;
        #pragma unroll
        for (int o = 16; o; o >>= 1) d += __shfl_xor_sync(0xffffffffu, d, o);
        if (lane == 0) {
            int h = t >> 1;
            if (t & 1) g_ed[n * 4 + h] = d;
            else       g_es[n * 4 + h] = d;
        }
    }
}

// ------------------------------- setup kernels -------------------------------
__global__ void init_kernel() {
    int i = blockIdx.x * blockDim.x + threadIdx.x;
    if (i < NN) g_deg[i] = 0;
    if (i < BB) { g_gstart[i] = NN; g_gend[i] = 0; }
    if (i < 3 * 128) { g_bnsum[i] = 0.f; g_bnsq[i] = 0.f; }
}

// also computes layer-0 es/ed (needs g_wa ready -> wa_prep runs before)
__global__ void copy_h_kernel(const float4* __restrict__ x) {
    int idx = blockIdx.x * blockDim.x + threadIdx.x;
    if (idx >= NN * 32) return;
    float4 v = x[idx];
    ((float4*)g_h)[idx] = v;
    uint2 hi, lo;
    split2(v.x, v.y, hi.x, lo.x);
    split2(v.z, v.w, hi.y, lo.y);
    ((uint2*)g_hhi)[idx] = hi;
    ((uint2*)g_hlo)[idx] = lo;
    warp_esed(v, idx & 31, idx >> 5, g_wa);
}

__global__ void nodebias_kernel(const float* __restrict__ Gemb) {
    int gid  = blockIdx.x * blockDim.x + threadIdx.x;
    int w    = gid >> 5;
    int lane = gid & 31;
    if (w >= NGG) return;
    float v = Gemb[w * 64 + lane] + Gemb[w * 64 + 32 + lane];
    #pragma unroll
    for (int o = 16; o; o >>= 1) v += __shfl_xor_sync(0xffffffffu, v, o);
    if (lane == 0) g_nodebias[w] = v * (1.0f / 64.0f);
}

__global__ void hist_kernel(const int* __restrict__ ei) {
    int e = blockIdx.x * blockDim.x + threadIdx.x;
    if (e >= ETOT) return;
    int dst = (e < EE) ? ei[EE + e] : (e - EE);
    atomicAdd(&g_deg[dst], 1);
}

__global__ void scan1_kernel() {   // 20 blocks x 1024
    __shared__ int sh[1024];
    int b = blockIdx.x, t = threadIdx.x;
    int i = b * 1024 + t;
    int v = (i < NN) ? g_deg[i] : 0;
    sh[t] = v;
    __syncthreads();
    for (int o = 1; o < 1024; o <<= 1) {
        int xv = (t >= o) ? sh[t - o] : 0;
        __syncthreads();
        sh[t] += xv;
        __syncthreads();
    }
    if (i < NN) g_off[i] = sh[t] - v;
    if (t == 1023) g_bsum[b] = sh[1023];
}

__global__ void scan2_kernel() {   // 1 block, 32 threads
    int t = threadIdx.x;
    int v = (t < 20) ? g_bsum[t] : 0;
    #pragma unroll
    for (int o = 1; o < 32; o <<= 1) {
        int xv = __shfl_up_sync(0xffffffffu, v, o);
        if (t >= o) v += xv;
    }
    if (t < 20) g_bpre[t] = v - g_bsum[t];
    if (t == 19) g_off[NN] = v;
}

__global__ void scan3_kernel() {
    int i = blockIdx.x * blockDim.x + threadIdx.x;
    if (i >= NN) return;
    int val = g_off[i] + g_bpre[i >> 10];
    g_off[i] = val;
    g_cur[i] = val;
}

__global__ void scatter_kernel(const int* __restrict__ ei) {
    int e = blockIdx.x * blockDim.x + threadIdx.x;
    if (e >= ETOT) return;
    int src, dst;
    if (e < EE) { src = ei[e]; dst = ei[EE + e]; }
    else        { src = e - EE; dst = e - EE; }
    int pos = atomicAdd(&g_cur[dst], 1);
    g_csr[pos] = src;
}

// ------------------- weight prep: all 3 layers at once -----------------------
__global__ void transpose_w3_kernel(const float* __restrict__ Wg) {
    int idx = blockIdx.x * blockDim.x + threadIdx.x;   // 3*512*64
    if (idx >= 3 * 512 * 64) return;
    int l  = idx >> 15;
    int r  = idx & 32767;
    int hn = r >> 6;            // h*128 + o
    int f  = (r & 63) * 2;
    int h = hn >> 7, o = hn & 127;
    const float* base = Wg + ((l * 4 + h) * 128) * 128 + o;
    float v0 = base[f * 128];
    float v1 = base[(f + 1) * 128];
    unsigned hi, lo;
    split2(v0, v1, hi, lo);
    g_Wnhi[idx] = hi;
    g_Wnlo[idx] = lo;
}

// wa[l][h*2+sd][f] = sum_o W[l,h,f,o] * a_{src|dst}[l,h,o]
__global__ void wa_prep_kernel(const float* __restrict__ Wg,
                               const float* __restrict__ asrc,
                               const float* __restrict__ adst) {
    int idx = blockIdx.x * blockDim.x + threadIdx.x;   // 3*8*128
    if (idx >= 3 * 8 * 128) return;
    int l = idx >> 10;
    int t = (idx >> 7) & 7;
    int f = idx & 127;
    int h = t >> 1, sd = t & 1;
    const float* a = (sd ? adst : asrc) + (l * 4 + h) * 128;
    const float* w = Wg + (((l * 4 + h) * 128) + f) * 128;
    float s = 0.f;
    #pragma unroll 4
    for (int o = 0; o < 128; o++) s += w[o] * a[o];
    g_wa[idx] = s;
}

// attA1 (128 x 256) -> [n][k] bf16 hi/lo
__global__ void a1prep_kernel(const float* __restrict__ attA1) {
    int idx = blockIdx.x * blockDim.x + threadIdx.x;   // 256*64
    if (idx >= 256 * 64) return;
    int n = idx >> 6;
    int k = (idx & 63) * 2;
    float v0 = attA1[k * 256 + n];
    float v1 = attA1[(k + 1) * 256 + n];
    unsigned hi, lo;
    split2(v0, v1, hi, lo);
    g_A1hi[idx] = hi;
    g_A1lo[idx] = lo;
}

// ---------------- BF16 tensor-core GEMM (ldmatrix, 3x split) -----------------
#define LDMX4(r, addr)                                                         \
    asm volatile("ldmatrix.sync.aligned.m8n8.x4.shared.b16 {%0,%1,%2,%3}, [%4];" \
                 : "=r"(r[0]), "=r"(r[1]), "=r"(r[2]), "=r"(r[3]) : "r"(addr))

#define MMA_BF16(c, a, b0, b1)                                                 \
    asm volatile("mma.sync.aligned.m16n8k16.row.col.f32.bf16.bf16.f32 "        \
                 "{%0,%1,%2,%3}, {%4,%5,%6,%7}, {%8,%9}, {%0,%1,%2,%3};"       \
                 : "+f"(c[0]), "+f"(c[1]), "+f"(c[2]), "+f"(c[3])              \
                 : "r"(a[0]), "r"(a[1]), "r"(a[2]), "r"(a[3]), "r"(b0), "r"(b1))

#define GEMM_SMEM_BYTES ((2 * 128 * 68 + 2 * 64 * 68) * 4)

template <int NC>
__global__ __launch_bounds__(256) void gemm_ldm_kernel(
        const unsigned* __restrict__ Bhi, const unsigned* __restrict__ Blo,
        float* __restrict__ C) {
    extern __shared__ unsigned sm[];
    unsigned* sAh = sm;                        // [128][68]
    unsigned* sAl = sAh + 128 * 68;
    unsigned* sBh = sAl + 128 * 68;            // [64][68]
    unsigned* sBl = sBh + 64 * 68;

    int tid  = threadIdx.x;
    int row0 = blockIdx.y * 128;
    int col0 = blockIdx.x * 64;

    for (int i = tid; i < 2048; i += 256) {
        int r = i >> 4, q = (i & 15) << 2;
        uint4 vh = make_uint4(0, 0, 0, 0), vl = make_uint4(0, 0, 0, 0);
        if (row0 + r < NN) {
            vh = *(const uint4*)&g_hhi[(row0 + r) * 64 + q];
            vl = *(const uint4*)&g_hlo[(row0 + r) * 64 + q];
        }
        *(uint4*)&sAh[r * 68 + q] = vh;
        *(uint4*)&sAl[r * 68 + q] = vl;
    }
    for (int i = tid; i < 1024; i += 256) {
        int n = i >> 4, q = (i & 15) << 2;
        *(uint4*)&sBh[n * 68 + q] = *(const uint4*)&Bhi[(col0 + n) * 64 + q];
        *(uint4*)&sBl[n * 68 + q] = *(const uint4*)&Blo[(col0 + n) * 64 + q];
    }
    __syncthreads();

    int lane = tid & 31, warp = tid >> 5;
    int arow  = warp * 16 + (lane & 15);
    int akoff = (lane & 16) ? 4 : 0;
    unsigned aAh = (unsigned)__cvta_generic_to_shared(&sAh[arow * 68 + akoff]);
    unsigned aAl = (unsigned)__cvta_generic_to_shared(&sAl[arow * 68 + akoff]);
    int bnr   = (lane & 7) + ((lane & 16) ? 8 : 0);
    int bkoff = (lane & 8) ? 4 : 0;
    unsigned aBh[4], aBl[4];
    #pragma unroll
    for (int p = 0; p < 4; p++) {
        aBh[p] = (unsigned)__cvta_generic_to_shared(&sBh[(p * 16 + bnr) * 68 + bkoff]);
        aBl[p] = (unsigned)__cvta_generic_to_shared(&sBl[(p * 16 + bnr) * 68 + bkoff]);
    }

    float acc[8][4];
    #pragma unroll
    for (int nt = 0; nt < 8; nt++)
        #pragma unroll
        for (int i = 0; i < 4; i++) acc[nt][i] = 0.0f;

    #pragma unroll
    for (int kc = 0; kc < 8; kc++) {
        unsigned koff = kc * 32;
        unsigned ah[4], al[4];
        LDMX4(ah, aAh + koff);
        LDMX4(al, aAl + koff);
        #pragma unroll
        for (int p = 0; p < 4; p++) {
            unsigned bh[4], bl[4];
            LDMX4(bh, aBh[p] + koff);
            LDMX4(bl, aBl[p] + koff);
            MMA_BF16(acc[2 * p],     ah, bh[0], bh[1]);
            MMA_BF16(acc[2 * p],     ah, bl[0], bl[1]);
            MMA_BF16(acc[2 * p],     al, bh[0], bh[1]);
            MMA_BF16(acc[2 * p + 1], ah, bh[2], bh[3]);
            MMA_BF16(acc[2 * p + 1], ah, bl[2], bl[3]);
            MMA_BF16(acc[2 * p + 1], al, bh[2], bh[3]);
        }
    }

    int gid = lane >> 2, tq = lane & 3;
    int ra = row0 + warp * 16 + gid;
    int rb = ra + 8;
    #pragma unroll
    for (int nt = 0; nt < 8; nt++) {
        int cc = col0 + nt * 8 + tq * 2;
        if (ra < NN) *(float2*)&C[ra * NC + cc] = make_float2(acc[nt][0], acc[nt][1]);
        if (rb < NN) *(float2*)&C[rb * NC + cc] = make_float2(acc[nt][2], acc[nt][3]);
    }
}

// ----------------------------- GAT aggregation -------------------------------
__device__ __forceinline__ float lrelu(float v) {
    return v > 0.f ? v : 0.2f * v;
}

// single pass: softmax is shift-invariant, scores are O(1) -> no max needed
__global__ void aggregate_kernel(const float* __restrict__ gbias, int l) {
    __shared__ float ssum[128], ssq[128];
    int tid  = threadIdx.x;
    if (tid < 128) { ssum[tid] = 0.f; ssq[tid] = 0.f; }
    __syncthreads();
    int gt   = blockIdx.x * blockDim.x + tid;
    int warp = gt >> 5;
    int lane = gt & 31;
    int nw = (gridDim.x * blockDim.x) >> 5;
    float4 csum = make_float4(0.f, 0.f, 0.f, 0.f);
    float4 csq  = make_float4(0.f, 0.f, 0.f, 0.f);
    float4 gb = ((const float4*)gbias)[lane];
    for (int n = warp; n < NN; n += nw) {
        int o0 = g_off[n], o1 = g_off[n + 1];
        float4 edn = *(const float4*)&g_ed[n * 4];

        float den[4] = {0.f, 0.f, 0.f, 0.f};
        float4 acc[4];
        #pragma unroll
        for (int h = 0; h < 4; h++) acc[h] = make_float4(0.f, 0.f, 0.f, 0.f);

        for (int e = o0; e < o1; e++) {
            int s = g_csr[e];
            float4 es = *(const float4*)&g_es[s * 4];
            float w0 = __expf(lrelu(es.x + edn.x));
            float w1 = __expf(lrelu(es.y + edn.y));
            float w2 = __expf(lrelu(es.z + edn.z));
            float w3 = __expf(lrelu(es.w + edn.w));
            den[0] += w0; den[1] += w1; den[2] += w2; den[3] += w3;
            const float4* xp = (const float4*)&g_xw[s * 512];
            float wv[4] = {w0, w1, w2, w3};
            #pragma unroll
            for (int h = 0; h < 4; h++) {
                float4 xv = xp[h * 32 + lane];
                acc[h].x += wv[h] * xv.x;
                acc[h].y += wv[h] * xv.y;
                acc[h].z += wv[h] * xv.z;
                acc[h].w += wv[h] * xv.w;
            }
        }

        float i0 = 1.f / den[0], i1 = 1.f / den[1], i2 = 1.f / den[2], i3 = 1.f / den[3];
        float4 v;
        v.x = (acc[0].x * i0 + acc[1].x * i1 + acc[2].x * i2 + acc[3].x * i3) * 0.25f + gb.x;
        v.y = (acc[0].y * i0 + acc[1].y * i1 + acc[2].y * i2 + acc[3].y * i3) * 0.25f + gb.y;
        v.z = (acc[0].z * i0 + acc[1].z * i1 + acc[2].z * i2 + acc[3].z * i3) * 0.25f + gb.z;
        v.w = (acc[0].w * i0 + acc[1].w * i1 + acc[2].w * i2 + acc[3].w * i3) * 0.25f + gb.w;
        *(float4*)&g_hn[n * 128 + lane * 4] = v;
        csum.x += v.x; csum.y += v.y; csum.z += v.z; csum.w += v.w;
        csq.x += v.x * v.x; csq.y += v.y * v.y; csq.z += v.z * v.z; csq.w += v.w * v.w;
    }
    atomicAdd(&ssum[lane * 4 + 0], csum.x);
    atomicAdd(&ssum[lane * 4 + 1], csum.y);
    atomicAdd(&ssum[lane * 4 + 2], csum.z);
    atomicAdd(&ssum[lane * 4 + 3], csum.w);
    atomicAdd(&ssq[lane * 4 + 0], csq.x);
    atomicAdd(&ssq[lane * 4 + 1], csq.y);
    atomicAdd(&ssq[lane * 4 + 2], csq.z);
    atomicAdd(&ssq[lane * 4 + 3], csq.w);
    __syncthreads();
    if (tid < 128) {
        atomicAdd(&g_bnsum[l * 128 + tid], ssum[tid]);
        atomicAdd(&g_bnsq[l * 128 + tid],  ssq[tid]);
    }
}

// BN finalize + apply + re-split + (es/ed for next layer, fused)
__global__ void bn_apply_kernel(const float* __restrict__ scale,
                                const float* __restrict__ bias,
                                int l, int nextl) {
    __shared__ float sinv[128], soff[128];
    int tid = threadIdx.x;
    if (tid < 128) {
        float mu  = g_bnsum[l * 128 + tid] * (1.0f / NN);
        float var = g_bnsq[l * 128 + tid] * (1.0f / NN) - mu * mu;
        float iv  = rsqrtf(var + 1e-5f) * scale[tid];
        sinv[tid] = iv;
        soff[tid] = bias[tid] - mu * iv;
    }
    __syncthreads();
    int idx = blockIdx.x * blockDim.x + tid;
    if (idx >= NN * 32) return;
    int c4 = (idx & 31) * 4;
    float4 v = ((const float4*)g_hn)[idx];
    float4 r;
    r.x = fmaxf(v.x * sinv[c4 + 0] + soff[c4 + 0], 0.f);
    r.y = fmaxf(v.y * sinv[c4 + 1] + soff[c4 + 1], 0.f);
    r.z = fmaxf(v.z * sinv[c4 + 2] + soff[c4 + 2], 0.f);
    r.w = fmaxf(v.w * sinv[c4 + 3] + soff[c4 + 3], 0.f);
    if (l > 0) {
        float4 h = ((const float4*)g_h)[idx];
        r.x += h.x; r.y += h.y; r.z += h.z; r.w += h.w;
    }
    ((float4*)g_h)[idx] = r;
    uint2 hi, lo;
    split2(r.x, r.y, hi.x, lo.x);
    split2(r.z, r.w, hi.y, lo.y);
    ((uint2*)g_hhi)[idx] = hi;
    ((uint2*)g_hlo)[idx] = lo;
    if (nextl >= 0)
        warp_esed(r, idx & 31, idx >> 5, g_wa + nextl * 1024);
}

// ------------------------------- pooling head -------------------------------
__global__ void score_kernel(const float* __restrict__ ab1,
                             const float* __restrict__ aA2,
                             const float* __restrict__ ab2) {
    int gt   = blockIdx.x * blockDim.x + threadIdx.x;
    int w    = gt >> 5;
    int lane = gt & 31;
    if (w >= NN) return;
    float acc = 0.f;
    #pragma unroll
    for (int j = lane; j < 256; j += 32)
        acc += tanhf(g_t[w * 256 + j] + ab1[j]) * aA2[j];
    #pragma unroll
    for (int o = 16; o; o >>= 1) acc += __shfl_xor_sync(0xffffffffu, acc, o);
    if (lane == 0) g_s[w] = acc + ab2[0];
}

__global__ void bounds_kernel(const int* __restrict__ batch) {
    int n = blockIdx.x * blockDim.x + threadIdx.x;
    if (n >= NN) return;
    int g = batch[n];
    atomicMin(&g_gstart[g], n);
    atomicMax(&g_gend[g], n + 1);
}

__global__ void pool_kernel(const int* __restrict__ brand0,
                            const int* __restrict__ brand1,
                            const float* __restrict__ Eb0,
                            const float* __restrict__ Eb1) {
    int g = blockIdx.x;
    int t = threadIdx.x;    // 128
    __shared__ float red[128];
    int st = g_gstart[g], en = g_gend[g];

    float m = -1e30f;
    for (int n = st + t; n < en; n += 128) m = fmaxf(m, g_s[n]);
    red[t] = m; __syncthreads();
    for (int o = 64; o; o >>= 1) { if (t < o) red[t] = fmaxf(red[t], red[t + o]); __syncthreads(); }
    m = red[0]; __syncthreads();

    float d = 0.f;
    for (int n = st + t; n < en; n += 128) d += __expf(g_s[n] - m);
    red[t] = d; __syncthreads();
    for (int o = 64; o; o >>= 1) { if (t < o) red[t] += red[t + o]; __syncthreads(); }
    d = red[0]; __syncthreads();

    float inv = (en > st) ? 1.0f / d : 0.0f;
    float acc = 0.f;
    for (int n = st; n < en; n++) {
        float w = __expf(g_s[n] - m) * inv;
        acc += w * g_h[n * 128 + t];
    }
    g_comb[g * 192 + t] = acc;
    if (t < 32)       g_comb[g * 192 + 128 + t]        = Eb0[brand0[g] * 32 + t];
    else if (t < 64)  g_comb[g * 192 + 160 + (t - 32)] = Eb1[brand1[g] * 32 + (t - 32)];
}

// --------------------------------- MLP head ---------------------------------
__global__ void mlp1_kernel(const float* __restrict__ P1w, const float* __restrict__ P1b) {
    int g = blockIdx.x;
    int j = threadIdx.x;    // 256
    __shared__ float cs[192];
    if (j < 192) cs[j] = g_comb[g * 192 + j];
    __syncthreads();
    float a = P1b[j];
    #pragma unroll 8
    for (int k = 0; k < 192; k++) a += cs[k] * P1w[k * 256 + j];
    g_z1p[g * 256 + j] = a;
}

__global__ void bnrelu1_kernel(const float* __restrict__ sc, const float* __restrict__ bi) {
    int j = blockIdx.x;     // 256 blocks
    int t = threadIdx.x;    // 128 threads
    __shared__ float red[128];
    float x = g_z1p[t * 256 + j];
    red[t] = x; __syncthreads();
    for (int o = 64; o; o >>= 1) { if (t < o) red[t] += red[t + o]; __syncthreads(); }
    float mu = red[0] * (1.0f / 128.0f); __syncthreads();
    red[t] = x * x; __syncthreads();
    for (int o = 64; o; o >>= 1) { if (t < o) red[t] += red[t + o]; __syncthreads(); }
    float var = red[0] * (1.0f / 128.0f) - mu * mu;
    float v = (x - mu) * rsqrtf(var + 1e-5f) * sc[j] + bi[j];
    g_z1[t * 256 + j] = fmaxf(v, 0.0f);
}

__global__ void mlp2_kernel(const float* __restrict__ P2w, const float* __restrict__ P2b) {
    int g = blockIdx.x;
    int j = threadIdx.x;    // 128
    __shared__ float zs[256];
    zs[j]       = g_z1[g * 256 + j];
    zs[j + 128] = g_z1[g * 256 + j + 128];
    __syncthreads();
    float a = P2b[j];
    #pragma unroll 8
    for (int k = 0; k < 256; k++) a += zs[k] * P2w[k * 128 + j];
    g_z2p[g * 128 + j] = a;
}

__global__ void bnrelu2_kernel(const float* __restrict__ sc, const float* __restrict__ bi) {
    int j = blockIdx.x;     // 128 blocks
    int t = threadIdx.x;    // 128 threads
    __shared__ float red[128];
    float x = g_z2p[t * 128 + j];
    red[t] = x; __syncthreads();
    for (int o = 64; o; o >>= 1) { if (t < o) red[t] += red[t + o]; __syncthreads(); }
    float mu = red[0] * (1.0f / 128.0f); __syncthreads();
    red[t] = x * x; __syncthreads();
    for (int o = 64; o; o >>= 1) { if (t < o) red[t] += red[t + o]; __syncthreads(); }
    float var = red[0] * (1.0f / 128.0f) - mu * mu;
    float v = (x - mu) * rsqrtf(var + 1e-5f) * sc[j] + bi[j];
    g_z2[t * 128 + j] = fmaxf(v, 0.0f);
}

__global__ void final_kernel(const float* __restrict__ P3w,
                             const float* __restrict__ P3b,
                             float* __restrict__ out) {
    __shared__ float zs[16][128];
    int col = blockIdx.x * 256 + threadIdx.x;
    int r0  = blockIdx.y * 16;
    for (int i = threadIdx.x; i < 16 * 128; i += 256) {
        int r = i >> 7, k = i & 127;
        zs[r][k] = g_z2[(r0 + r) * 128 + k];
    }
    __syncthreads();
    if (col >= NGG) return;
    float acc[16];
    #pragma unroll
    for (int r = 0; r < 16; r++) acc[r] = 0.f;
    for (int k = 0; k < 128; k++) {
        float b = P3w[k * NGG + col];
        #pragma unroll
        for (int r = 0; r < 16; r++) acc[r] += zs[r][k] * b;
    }
    float add = P3b[col] + 0.1f * g_nodebias[col];
    #pragma unroll
    for (int r = 0; r < 16; r++) out[(r0 + r) * NGG + col] = acc[r] + add;
}

// ------------------------------- kernel_launch -------------------------------
extern "C" void kernel_launch(void* const* d_in, const int* in_sizes, int n_in,
                              void* d_out, int out_size) {
    const float* x        = (const float*)d_in[0];
    const int*   ei       = (const int*)  d_in[1];
    const int*   batch    = (const int*)  d_in[2];
    const int*   brand0   = (const int*)  d_in[3];
    const int*   brand1   = (const int*)  d_in[4];
    const float* Wg       = (const float*)d_in[5];
    const float* att_src  = (const float*)d_in[6];
    const float* att_dst  = (const float*)d_in[7];
    const float* gat_bias = (const float*)d_in[8];
    const float* bn_scale = (const float*)d_in[9];
    const float* bn_bias  = (const float*)d_in[10];
    const float* attA1    = (const float*)d_in[11];
    const float* attb1    = (const float*)d_in[12];
    const float* attA2    = (const float*)d_in[13];
    const float* attb2    = (const float*)d_in[14];
    const float* Eb0      = (const float*)d_in[15];
    const float* Eb1      = (const float*)d_in[16];
    const float* P1w      = (const float*)d_in[17];
    const float* P1b      = (const float*)d_in[18];
    const float* pbn1_s   = (const float*)d_in[19];
    const float* pbn1_b   = (const float*)d_in[20];
    const float* P2w      = (const float*)d_in[21];
    const float* P2b      = (const float*)d_in[22];
    const float* pbn2_s   = (const float*)d_in[23];
    const float* pbn2_b   = (const float*)d_in[24];
    const float* P3w      = (const float*)d_in[25];
    const float* P3b      = (const float*)d_in[26];
    const float* Gemb     = (const float*)d_in[27];
    float* out = (float*)d_out;

    float* d_xw = nullptr; cudaGetSymbolAddress((void**)&d_xw, g_xw);
    float* d_t  = nullptr; cudaGetSymbolAddress((void**)&d_t,  g_t);
    unsigned *d_wh = nullptr, *d_wl = nullptr, *d_a1h = nullptr, *d_a1l = nullptr;
    cudaGetSymbolAddress((void**)&d_wh,  g_Wnhi);
    cudaGetSymbolAddress((void**)&d_wl,  g_Wnlo);
    cudaGetSymbolAddress((void**)&d_a1h, g_A1hi);
    cudaGetSymbolAddress((void**)&d_a1l, g_A1lo);

    cudaFuncSetAttribute(gemm_ldm_kernel<512>,
                         cudaFuncAttributeMaxDynamicSharedMemorySize, GEMM_SMEM_BYTES);
    cudaFuncSetAttribute(gemm_ldm_kernel<256>,
                         cudaFuncAttributeMaxDynamicSharedMemorySize, GEMM_SMEM_BYTES);

    // setup (wa_prep before copy_h: copy_h computes layer-0 es/ed from g_wa)
    init_kernel<<<(NN + 255) / 256, 256>>>();
    wa_prep_kernel<<<(3 * 8 * 128 + 255) / 256, 256>>>(Wg, att_src, att_dst);
    copy_h_kernel<<<(NN * 32 + 255) / 256, 256>>>((const float4*)x);
    nodebias_kernel<<<(NGG * 32 + 255) / 256, 256>>>(Gemb);
    hist_kernel<<<(ETOT + 255) / 256, 256>>>(ei);
    scan1_kernel<<<20, 1024>>>();
    scan2_kernel<<<1, 32>>>();
    scan3_kernel<<<(NN + 255) / 256, 256>>>();
    scatter_kernel<<<(ETOT + 255) / 256, 256>>>(ei);
    transpose_w3_kernel<<<(3 * 512 * 64 + 255) / 256, 256>>>(Wg);
    a1prep_kernel<<<(256 * 64 + 255) / 256, 256>>>(attA1);

    // GAT layers
    for (int l = 0; l < 3; l++) {
        gemm_ldm_kernel<512><<<dim3(8, (NN + 127) / 128), 256, GEMM_SMEM_BYTES>>>(
            d_wh + l * 32768, d_wl + l * 32768, d_xw);
        aggregate_kernel<<<512, 256>>>(gat_bias + l * 128, l);
        bn_apply_kernel<<<(NN * 32 + 255) / 256, 256>>>(bn_scale + l * 128,
                                                        bn_bias + l * 128,
                                                        l, l < 2 ? l + 1 : -1);
    }

    // attention pooling
    gemm_ldm_kernel<256><<<dim3(4, (NN + 127) / 128), 256, GEMM_SMEM_BYTES>>>(
        d_a1h, d_a1l, d_t);
    score_kernel<<<(NN * 32 + 255) / 256, 256>>>(attb1, attA2, attb2);
    bounds_kernel<<<(NN + 255) / 256, 256>>>(batch);
    pool_kernel<<<BB, 128>>>(brand0, brand1, Eb0, Eb1);

    // MLP head
    mlp1_kernel<<<BB, 256>>>(P1w, P1b);
    bnrelu1_kernel<<<256, 128>>>(pbn1_s, pbn1_b);
    mlp2_kernel<<<BB, 128>>>(P2w, P2b);
    bnrelu2_kernel<<<128, 128>>>(pbn2_s, pbn2_b);
    final_kernel<<<dim3((NGG + 255) / 256, 8), 256>>>(P3w, P3b, out);
}